// round 7
// baseline (speedup 1.0000x reference)
#include <cuda_runtime.h>
#include <cuda_bf16.h>
#include <cstdint>

#define N_NODES 50000
#define N_EDGES 800000
#define N_GRAPHS 128
#define D 128
#define L 4
#define C 10
#define GN_EPS 1e-5f
#define NB_SCAN 196
#define PAD 132
#define ZERO_ELEMS (L * N_GRAPHS * 2 * D)   // 131072, largest scratch to clear

// ------------------------- device scratch (static, no allocs) -------------
__device__ float g_h[(size_t)N_NODES * D];   // normalized state (gin input)
__device__ float g_a[(size_t)N_NODES * D];   // gin output H (gnapply input)
__device__ int   g_rowptr[N_NODES + 1];
__device__ int   g_cursor[N_NODES];
__device__ int   g_cnt[N_NODES];
__device__ int   g_col[N_EDGES];
__device__ int   g_bsum[NB_SCAN];
__device__ int   g_boff[NB_SCAN];
__device__ int   g_gptr[N_GRAPHS + 1];
__device__ float g_gcnt[N_GRAPHS];
__device__ float g_pool[N_GRAPHS * D];
__device__ float g_stat[L][N_GRAPHS][2][D];     // [l][g][{sum,sumsq}][d]
__device__ float g_wT[8][16384];                // W^T (tf32-rounded), B[n][k]
__device__ int   g_is64e;
__device__ int   g_is64b;

// ------------------------- helpers ----------------------------------------
__device__ __forceinline__ int e_at(const void* p, long long i) {
    if (g_is64e) return (int)((const long long*)p)[i];
    return ((const int*)p)[i];
}
__device__ __forceinline__ int b_at(const void* p, long long i) {
    if (g_is64b) return (int)((const long long*)p)[i];
    return ((const int*)p)[i];
}
__device__ __forceinline__ float to_tf32(float x) {
    float r; asm("cvt.rna.tf32.f32 %0, %1;" : "=f"(r) : "f"(x)); return r;
}

// mma.sync m16n8k8 tf32: D = A*B + D
__device__ __forceinline__ void mma_tf32(float c[4], const float a[4],
                                         uint32_t b0, uint32_t b1) {
    const uint32_t* A = reinterpret_cast<const uint32_t*>(a);
    asm volatile(
        "mma.sync.aligned.m16n8k8.row.col.f32.tf32.tf32.f32 "
        "{%0,%1,%2,%3}, {%4,%5,%6,%7}, {%8,%9}, {%0,%1,%2,%3};"
        : "+f"(c[0]), "+f"(c[1]), "+f"(c[2]), "+f"(c[3])
        : "r"(A[0]), "r"(A[1]), "r"(A[2]), "r"(A[3]), "r"(b0), "r"(b1));
}

// ------------------------- prep: zero scratch + dtype detect ---------------
__global__ void k_prep(const int* __restrict__ ew, const int* __restrict__ bw) {
    int i = blockIdx.x * blockDim.x + threadIdx.x;
    if (i < N_NODES) g_cnt[i] = 0;
    if (i < ZERO_ELEMS) (&g_stat[0][0][0][0])[i] = 0.f;
    if (i < N_GRAPHS * D) g_pool[i] = 0.f;
    if (blockIdx.x == 0) {
        __shared__ int s_ez, s_bg;
        if (threadIdx.x == 0) { s_ez = 1; s_bg = 0; }
        __syncthreads();
        for (int j = threadIdx.x; j < 128; j += blockDim.x)
            if (ew[2 * j + 1] != 0) atomicAnd(&s_ez, 0);
        for (int j = threadIdx.x; j < 24999; j += blockDim.x)
            if (bw[2 * j] > bw[2 * j + 1]) atomicOr(&s_bg, 1);
        __syncthreads();
        if (threadIdx.x == 0) { g_is64e = s_ez; g_is64b = s_bg; }
    }
}

// ------------------------- weight transpose (tf32-rounded) -----------------
__global__ void k_wt(const float* __restrict__ w1, const float* __restrict__ w2) {
    int m = blockIdx.x;                     // 0..7
    const float* W = (m < 4) ? (w1 + (size_t)m * D * D) : (w2 + (size_t)(m - 4) * D * D);
    for (int idx = threadIdx.x; idx < D * D; idx += blockDim.x) {
        int k = idx >> 7, n = idx & 127;
        g_wT[m][n * D + k] = to_tf32(W[idx]);   // B[n][k] = W[k][n]
    }
}

// ------------------------- CSR build ---------------------------------------
__global__ void k_hist(const void* __restrict__ e) {
    int i = blockIdx.x * blockDim.x + threadIdx.x;
    if (i < N_EDGES) atomicAdd(&g_cnt[e_at(e, (long long)N_EDGES + i)], 1);
}
__global__ void k_scan1() {
    __shared__ int sm[256];
    int t = threadIdx.x, idx = blockIdx.x * 256 + t;
    int v = (idx < N_NODES) ? g_cnt[idx] : 0;
    sm[t] = v; __syncthreads();
    for (int off = 1; off < 256; off <<= 1) {
        int u = (t >= off) ? sm[t - off] : 0;
        __syncthreads(); sm[t] += u; __syncthreads();
    }
    if (idx < N_NODES) g_cnt[idx] = sm[t] - v;
    if (t == 255) g_bsum[blockIdx.x] = sm[255];
}
__global__ void k_scan2() {
    __shared__ int sm[256];
    int t = threadIdx.x;
    int v = (t < NB_SCAN) ? g_bsum[t] : 0;
    sm[t] = v; __syncthreads();
    for (int off = 1; off < 256; off <<= 1) {
        int u = (t >= off) ? sm[t - off] : 0;
        __syncthreads(); sm[t] += u; __syncthreads();
    }
    if (t < NB_SCAN) g_boff[t] = sm[t] - v;
    if (t == NB_SCAN - 1) g_rowptr[N_NODES] = sm[t];
}
__global__ void k_scan3() {
    int idx = blockIdx.x * 256 + threadIdx.x;
    if (idx < N_NODES) {
        int rp = g_boff[blockIdx.x] + g_cnt[idx];
        g_rowptr[idx] = rp; g_cursor[idx] = rp;
    }
}
__global__ void k_fill(const void* __restrict__ e) {
    int i = blockIdx.x * blockDim.x + threadIdx.x;
    if (i < N_EDGES) {
        int s = e_at(e, i);
        int d = e_at(e, (long long)N_EDGES + i);
        g_col[atomicAdd(&g_cursor[d], 1)] = s;
    }
}

// ------------------------- graph ranges via binary search ------------------
__global__ void k_graphs(const void* __restrict__ batch) {
    int g = threadIdx.x;                   // 0..127
    int lo = 0, hi = N_NODES;
    while (lo < hi) {
        int mid = (lo + hi) >> 1;
        if (b_at(batch, mid) < g) lo = mid + 1; else hi = mid;
    }
    g_gptr[g] = lo;
    if (g == 0) g_gptr[N_GRAPHS] = N_NODES;
    __syncthreads();
    int nxt = (g < N_GRAPHS - 1) ? g_gptr[g + 1] : N_NODES;
    g_gcnt[g] = fmaxf((float)(nxt - lo), 1.0f);
}

// ---- fused GIN layer: gather + gemm1 + relu + gemm2 + relu + stats --------
// Reads Hin (g_h or x), writes Hout (g_a). NEVER the same buffer: the gather
// reads arbitrary rows of Hin while other CTAs write Hout.
#define SMEM_GIN (3 * 128 * PAD * 4)

__global__ void __launch_bounds__(256) k_gin(const float* __restrict__ Hin,
                                             int layer,
                                             const float* __restrict__ bias1,
                                             const float* __restrict__ bias2,
                                             const void* __restrict__ batch,
                                             float* __restrict__ Hout) {
    extern __shared__ float sm[];
    float* As  = sm;                  // [128][PAD]  gathered A tile, then H1
    float* Bs1 = sm + 128 * PAD;      // [128][PAD]  W1^T; later final-H staging
    float* Bs2 = sm + 2 * 128 * PAD;  // [128][PAD]  W2^T
    __shared__ float b1s[128], b2s[128];
    __shared__ int gids[128];

    int tid = threadIdx.x, wid = tid >> 5, lane = tid & 31;
    int warp_m = wid & 3, warp_n = wid >> 2;
    int gID = lane >> 2, tig = lane & 3;
    int rb = blockIdx.x * 128;
    int nvalid = min(128, N_NODES - rb);

    // stage W1^T, W2^T (L2-hot linear copies)
#pragma unroll
    for (int it = 0; it < 16; it++) {
        int idx = tid + it * 256;          // 0..4095
        int r = idx >> 5, c4 = (idx & 31) * 4;
        *(float4*)(Bs1 + r * PAD + c4) = *(const float4*)(g_wT[layer] + idx * 4);
        *(float4*)(Bs2 + r * PAD + c4) = *(const float4*)(g_wT[4 + layer] + idx * 4);
    }
    if (tid < 128) {
        b1s[tid] = bias1[tid];
        gids[tid] = (tid < nvalid) ? b_at(batch, rb + tid) : 0;
    } else {
        b2s[tid - 128] = bias2[tid - 128];
    }

    // fused edge gather: warp w handles rows w, w+8, ..., w+120
    for (int rr = wid; rr < 128; rr += 8) {
        int gr = rb + rr;
        float4 acc = make_float4(0.f, 0.f, 0.f, 0.f);
        if (gr < N_NODES) {
            acc = __ldg(((const float4*)(Hin + (size_t)gr * D)) + lane);
            int s = g_rowptr[gr], e = g_rowptr[gr + 1];
            int i = s;
            for (; i + 4 <= e; i += 4) {
                int s0 = g_col[i], s1 = g_col[i + 1];
                int s2 = g_col[i + 2], s3 = g_col[i + 3];
                float4 v0 = __ldg(((const float4*)(Hin + (size_t)s0 * D)) + lane);
                float4 v1 = __ldg(((const float4*)(Hin + (size_t)s1 * D)) + lane);
                float4 v2 = __ldg(((const float4*)(Hin + (size_t)s2 * D)) + lane);
                float4 v3 = __ldg(((const float4*)(Hin + (size_t)s3 * D)) + lane);
                acc.x += v0.x + v1.x + v2.x + v3.x;
                acc.y += v0.y + v1.y + v2.y + v3.y;
                acc.z += v0.z + v1.z + v2.z + v3.z;
                acc.w += v0.w + v1.w + v2.w + v3.w;
            }
            for (; i < e; i++) {
                float4 v = __ldg(((const float4*)(Hin + (size_t)g_col[i] * D)) + lane);
                acc.x += v.x; acc.y += v.y; acc.z += v.z; acc.w += v.w;
            }
        }
        float* dst = As + rr * PAD + lane * 4;
        dst[0] = to_tf32(acc.x); dst[1] = to_tf32(acc.y);
        dst[2] = to_tf32(acc.z); dst[3] = to_tf32(acc.w);
    }
    __syncthreads();

    float c[2][8][4];
    float a[2][4];

    // ---------------- GEMM1: H1 = relu(A @ W1 + b1) ----------------
#pragma unroll
    for (int i = 0; i < 2; i++)
#pragma unroll
        for (int j = 0; j < 8; j++)
#pragma unroll
            for (int q = 0; q < 4; q++) c[i][j][q] = 0.f;

#pragma unroll 2
    for (int kk = 0; kk < 16; kk++) {
        int k0 = kk * 8;
#pragma unroll
        for (int i = 0; i < 2; i++) {
            int row = warp_m * 32 + i * 16;
            a[i][0] = As[(row + gID) * PAD + k0 + tig];
            a[i][1] = As[(row + gID + 8) * PAD + k0 + tig];
            a[i][2] = As[(row + gID) * PAD + k0 + tig + 4];
            a[i][3] = As[(row + gID + 8) * PAD + k0 + tig + 4];
        }
#pragma unroll
        for (int j = 0; j < 8; j++) {
            int n = warp_n * 64 + j * 8 + gID;
            uint32_t b0 = __float_as_uint(Bs1[n * PAD + k0 + tig]);
            uint32_t b1 = __float_as_uint(Bs1[n * PAD + k0 + tig + 4]);
            mma_tf32(c[0][j], a[0], b0, b1);
            mma_tf32(c[1][j], a[1], b0, b1);
        }
    }
    __syncthreads();   // all reads of As / Bs1 complete

    // write H1 (tf32-rounded) back into As
#pragma unroll
    for (int i = 0; i < 2; i++) {
        int r0 = warp_m * 32 + i * 16 + gID;
#pragma unroll
        for (int j = 0; j < 8; j++) {
            int cb = warp_n * 64 + j * 8 + 2 * tig;
            As[r0 * PAD + cb]       = to_tf32(fmaxf(c[i][j][0] + b1s[cb], 0.f));
            As[r0 * PAD + cb + 1]   = to_tf32(fmaxf(c[i][j][1] + b1s[cb + 1], 0.f));
            As[(r0 + 8) * PAD + cb]     = to_tf32(fmaxf(c[i][j][2] + b1s[cb], 0.f));
            As[(r0 + 8) * PAD + cb + 1] = to_tf32(fmaxf(c[i][j][3] + b1s[cb + 1], 0.f));
        }
    }
    __syncthreads();

    // ---------------- GEMM2: H = relu(H1 @ W2 + b2) ----------------
#pragma unroll
    for (int i = 0; i < 2; i++)
#pragma unroll
        for (int j = 0; j < 8; j++)
#pragma unroll
            for (int q = 0; q < 4; q++) c[i][j][q] = 0.f;

#pragma unroll 2
    for (int kk = 0; kk < 16; kk++) {
        int k0 = kk * 8;
#pragma unroll
        for (int i = 0; i < 2; i++) {
            int row = warp_m * 32 + i * 16;
            a[i][0] = As[(row + gID) * PAD + k0 + tig];
            a[i][1] = As[(row + gID + 8) * PAD + k0 + tig];
            a[i][2] = As[(row + gID) * PAD + k0 + tig + 4];
            a[i][3] = As[(row + gID + 8) * PAD + k0 + tig + 4];
        }
#pragma unroll
        for (int j = 0; j < 8; j++) {
            int n = warp_n * 64 + j * 8 + gID;
            uint32_t b0 = __float_as_uint(Bs2[n * PAD + k0 + tig]);
            uint32_t b1 = __float_as_uint(Bs2[n * PAD + k0 + tig + 4]);
            mma_tf32(c[0][j], a[0], b0, b1);
            mma_tf32(c[1][j], a[1], b0, b1);
        }
    }

    // epilogue: H -> global + smem (Bs1 reused as staging for stats)
    float* Hs = Bs1;
#pragma unroll
    for (int i = 0; i < 2; i++) {
        int lr0 = warp_m * 32 + i * 16 + gID;
        int lr1 = lr0 + 8;
#pragma unroll
        for (int j = 0; j < 8; j++) {
            int cb = warp_n * 64 + j * 8 + 2 * tig;
            float2 o0, o1;
            o0.x = fmaxf(c[i][j][0] + b2s[cb], 0.f);
            o0.y = fmaxf(c[i][j][1] + b2s[cb + 1], 0.f);
            o1.x = fmaxf(c[i][j][2] + b2s[cb], 0.f);
            o1.y = fmaxf(c[i][j][3] + b2s[cb + 1], 0.f);
            Hs[lr0 * PAD + cb] = o0.x;  Hs[lr0 * PAD + cb + 1] = o0.y;
            Hs[lr1 * PAD + cb] = o1.x;  Hs[lr1 * PAD + cb + 1] = o1.y;
            if (lr0 < nvalid) *(float2*)(Hout + (size_t)(rb + lr0) * D + cb) = o0;
            if (lr1 < nvalid) *(float2*)(Hout + (size_t)(rb + lr1) * D + cb) = o1;
        }
    }
    __syncthreads();

    // per-graph stats (sum, sumsq) from smem, 2 strips of 64 rows
    {
        int d = tid & 127, half = tid >> 7;
        int r0 = half * 64, r1 = min(r0 + 64, nvalid);
        if (r0 < nvalid) {
            int curg = gids[r0];
            float s = 0.f, q = 0.f;
            for (int r = r0; r < r1; r++) {
                int g = gids[r];
                if (g != curg) {
                    atomicAdd(&g_stat[layer][curg][0][d], s);
                    atomicAdd(&g_stat[layer][curg][1][d], q);
                    s = 0.f; q = 0.f; curg = g;
                }
                float v = Hs[r * PAD + d];
                s += v; q += v * v;
            }
            atomicAdd(&g_stat[layer][curg][0][d], s);
            atomicAdd(&g_stat[layer][curg][1][d], q);
        }
    }
}

// ------------------------- GraphNorm apply + relu (+pool on last) ----------
// Reads g_a (gin output), writes g_h (next gin input) or pool.
__global__ void __launch_bounds__(256) k_gnapply(const void* __restrict__ batch,
                                                 const float* __restrict__ w,
                                                 const float* __restrict__ b,
                                                 const float* __restrict__ ms,
                                                 int layer, int last) {
    int warp = (blockIdx.x * blockDim.x + threadIdx.x) >> 5;
    int lane = threadIdx.x & 31;
    if (warp >= N_NODES) return;
    int g = b_at(batch, warp);
    float c = g_gcnt[g];
    int d0 = lane * 4;
    float4 h  = ((const float4*)(g_a + (size_t)warp * D))[lane];
    float4 s4 = *(const float4*)&g_stat[layer][g][0][d0];
    float4 q4 = *(const float4*)&g_stat[layer][g][1][d0];
    float4 ms4 = *(const float4*)(ms + layer * D + d0);
    float4 w4  = *(const float4*)(w  + layer * D + d0);
    float4 b4  = *(const float4*)(b  + layer * D + d0);
    float4 o;
#define GN1(X) {                                                   \
    float mean = s4.X / c;                                         \
    float aa = mean * ms4.X;                                       \
    float var = q4.X / c - 2.f * aa * mean + aa * aa;              \
    float rstd = rsqrtf(var + GN_EPS);                             \
    o.X = fmaxf(w4.X * (h.X - aa) * rstd + b4.X, 0.f); }
    GN1(x) GN1(y) GN1(z) GN1(w)
#undef GN1
    if (last) {
        atomicAdd(&g_pool[g * D + d0 + 0], o.x);
        atomicAdd(&g_pool[g * D + d0 + 1], o.y);
        atomicAdd(&g_pool[g * D + d0 + 2], o.z);
        atomicAdd(&g_pool[g * D + d0 + 3], o.w);
    } else {
        ((float4*)(g_h + (size_t)warp * D))[lane] = o;
    }
}

// ------------------------- final MLP + log_softmax -------------------------
__global__ void __launch_bounds__(128) k_mlp(const float* __restrict__ fw1,
                                             const float* __restrict__ fb1,
                                             const float* __restrict__ fw2,
                                             const float* __restrict__ fb2,
                                             const float* __restrict__ fw3,
                                             const float* __restrict__ fb3,
                                             float* __restrict__ out) {
    int g = blockIdx.x, t = threadIdx.x;
    __shared__ float v[D], v2[D], o[C], red[2];
    v[t] = g_pool[g * D + t];
    __syncthreads();
    float acc = fb1[t];
    for (int k = 0; k < D; k++) acc += v[k] * fw1[k * D + t];
    v2[t] = fmaxf(acc, 0.f);
    __syncthreads();
    acc = fb2[t];
    for (int k = 0; k < D; k++) acc += v2[k] * fw2[k * D + t];
    __syncthreads();
    v[t] = fmaxf(acc, 0.f);
    __syncthreads();
    if (t < C) {
        float a = fb3[t];
        for (int k = 0; k < D; k++) a += v[k] * fw3[k * C + t];
        o[t] = a;
    }
    __syncthreads();
    if (t == 0) {
        float m = -1e30f;
        for (int c = 0; c < C; c++) m = fmaxf(m, o[c]);
        float se = 0.f;
        for (int c = 0; c < C; c++) se += expf(o[c] - m);
        red[0] = m; red[1] = logf(se);
    }
    __syncthreads();
    if (t < C) out[g * C + t] = o[t] - red[0] - red[1];
}

// ------------------------- launcher ----------------------------------------
extern "C" void kernel_launch(void* const* d_in, const int* in_sizes, int n_in,
                              void* d_out, int out_size) {
    const float* x    = (const float*)d_in[0];
    const float* w1   = (const float*)d_in[1];
    const float* b1   = (const float*)d_in[2];
    const float* w2   = (const float*)d_in[3];
    const float* b2   = (const float*)d_in[4];
    const float* gnw  = (const float*)d_in[5];
    const float* gnb  = (const float*)d_in[6];
    const float* gns  = (const float*)d_in[7];
    const float* fw1  = (const float*)d_in[8];
    const float* fb1  = (const float*)d_in[9];
    const float* fw2  = (const float*)d_in[10];
    const float* fb2  = (const float*)d_in[11];
    const float* fw3  = (const float*)d_in[12];
    const float* fb3  = (const float*)d_in[13];
    const void*  edge  = d_in[14];
    const void*  batch = d_in[15];
    float* out = (float*)d_out;

    float *p_h, *p_a;
    cudaGetSymbolAddress((void**)&p_h, g_h);
    cudaGetSymbolAddress((void**)&p_a, g_a);
    cudaFuncSetAttribute(k_gin, cudaFuncAttributeMaxDynamicSharedMemorySize,
                         SMEM_GIN);

    // prologue
    k_prep<<<(ZERO_ELEMS + 255) / 256, 256>>>((const int*)edge, (const int*)batch);
    k_wt<<<8, 256>>>(w1, w2);
    k_hist<<<(N_EDGES + 255) / 256, 256>>>(edge);
    k_scan1<<<NB_SCAN, 256>>>();
    k_scan2<<<1, 256>>>();
    k_scan3<<<NB_SCAN, 256>>>();
    k_fill<<<(N_EDGES + 255) / 256, 256>>>(edge);
    k_graphs<<<1, N_GRAPHS>>>(batch);

    const int ginGrid = (N_NODES + 127) / 128;        // 391
    const int gnGrid  = (N_NODES * 32 + 255) / 256;   // 6250

    for (int l = 0; l < L; l++) {
        const float* hin = (l == 0) ? x : p_h;
        // gin: reads hin (x or g_h), writes g_a  -- distinct buffers, no race
        k_gin<<<ginGrid, 256, SMEM_GIN>>>(hin, l,
                                          b1 + (size_t)l * D, b2 + (size_t)l * D,
                                          batch, p_a);
        // gnapply: reads g_a, writes g_h (or pool on last layer)
        k_gnapply<<<gnGrid, 256>>>(batch, gnw, gnb, gns, l, l == L - 1);
    }
    k_mlp<<<N_GRAPHS, 128>>>(fw1, fb1, fw2, fb2, fw3, fb3, out);
}

// round 8
// speedup vs baseline: 1.3615x; 1.3615x over previous
#include <cuda_runtime.h>
#include <cuda_bf16.h>
#include <cstdint>

#define N_NODES 50000
#define N_EDGES 800000
#define N_GRAPHS 128
#define D 128
#define L 4
#define C 10
#define GN_EPS 1e-5f
#define NB_SCAN 196
#define PAD 132
#define ZERO_ELEMS (L * N_GRAPHS * 2 * D)   // 131072, largest scratch to clear

// ------------------------- device scratch (static, no allocs) -------------
__device__ float g_h[(size_t)N_NODES * D];   // state (gnapply in-place)
__device__ float g_a[(size_t)N_NODES * D];   // agg output / gin input
__device__ int   g_rowptr[N_NODES + 1];
__device__ int   g_cursor[N_NODES];
__device__ int   g_cnt[N_NODES];
__device__ int   g_col[N_EDGES];
__device__ int   g_bsum[NB_SCAN];
__device__ int   g_boff[NB_SCAN];
__device__ int   g_gptr[N_GRAPHS + 1];
__device__ float g_gcnt[N_GRAPHS];
__device__ float g_pool[N_GRAPHS * D];
__device__ float g_stat[L][N_GRAPHS][2][D];     // [l][g][{sum,sumsq}][d]
__device__ float g_wT[8][16384];                // W^T (tf32-rounded), B[n][k]
__device__ int   g_is64e;
__device__ int   g_is64b;

// ------------------------- helpers ----------------------------------------
__device__ __forceinline__ int e_at(const void* p, long long i) {
    if (g_is64e) return (int)((const long long*)p)[i];
    return ((const int*)p)[i];
}
__device__ __forceinline__ int b_at(const void* p, long long i) {
    if (g_is64b) return (int)((const long long*)p)[i];
    return ((const int*)p)[i];
}
__device__ __forceinline__ float to_tf32(float x) {
    float r; asm("cvt.rna.tf32.f32 %0, %1;" : "=f"(r) : "f"(x)); return r;
}

// mma.sync m16n8k8 tf32: D = A*B + D
__device__ __forceinline__ void mma_tf32(float c[4], const float a[4],
                                         uint32_t b0, uint32_t b1) {
    const uint32_t* A = reinterpret_cast<const uint32_t*>(a);
    asm volatile(
        "mma.sync.aligned.m16n8k8.row.col.f32.tf32.tf32.f32 "
        "{%0,%1,%2,%3}, {%4,%5,%6,%7}, {%8,%9}, {%0,%1,%2,%3};"
        : "+f"(c[0]), "+f"(c[1]), "+f"(c[2]), "+f"(c[3])
        : "r"(A[0]), "r"(A[1]), "r"(A[2]), "r"(A[3]), "r"(b0), "r"(b1));
}

// ------------------------- prep: zero scratch + dtype detect ---------------
__global__ void k_prep(const int* __restrict__ ew, const int* __restrict__ bw) {
    int i = blockIdx.x * blockDim.x + threadIdx.x;
    if (i < N_NODES) g_cnt[i] = 0;
    if (i < ZERO_ELEMS) (&g_stat[0][0][0][0])[i] = 0.f;
    if (i < N_GRAPHS * D) g_pool[i] = 0.f;
    if (blockIdx.x == 0) {
        __shared__ int s_ez, s_bg;
        if (threadIdx.x == 0) { s_ez = 1; s_bg = 0; }
        __syncthreads();
        for (int j = threadIdx.x; j < 128; j += blockDim.x)
            if (ew[2 * j + 1] != 0) atomicAnd(&s_ez, 0);
        for (int j = threadIdx.x; j < 24999; j += blockDim.x)
            if (bw[2 * j] > bw[2 * j + 1]) atomicOr(&s_bg, 1);
        __syncthreads();
        if (threadIdx.x == 0) { g_is64e = s_ez; g_is64b = s_bg; }
    }
}

// ------------------------- weight transpose (tf32-rounded) -----------------
__global__ void k_wt(const float* __restrict__ w1, const float* __restrict__ w2) {
    int m = blockIdx.x;                     // 0..7
    const float* W = (m < 4) ? (w1 + (size_t)m * D * D) : (w2 + (size_t)(m - 4) * D * D);
    for (int idx = threadIdx.x; idx < D * D; idx += blockDim.x) {
        int k = idx >> 7, n = idx & 127;
        g_wT[m][n * D + k] = to_tf32(W[idx]);   // B[n][k] = W[k][n]
    }
}

// ------------------------- CSR build ---------------------------------------
__global__ void k_hist(const void* __restrict__ e) {
    int i = blockIdx.x * blockDim.x + threadIdx.x;
    if (i < N_EDGES) atomicAdd(&g_cnt[e_at(e, (long long)N_EDGES + i)], 1);
}
__global__ void k_scan1() {
    __shared__ int sm[256];
    int t = threadIdx.x, idx = blockIdx.x * 256 + t;
    int v = (idx < N_NODES) ? g_cnt[idx] : 0;
    sm[t] = v; __syncthreads();
    for (int off = 1; off < 256; off <<= 1) {
        int u = (t >= off) ? sm[t - off] : 0;
        __syncthreads(); sm[t] += u; __syncthreads();
    }
    if (idx < N_NODES) g_cnt[idx] = sm[t] - v;
    if (t == 255) g_bsum[blockIdx.x] = sm[255];
}
__global__ void k_scan2() {
    __shared__ int sm[256];
    int t = threadIdx.x;
    int v = (t < NB_SCAN) ? g_bsum[t] : 0;
    sm[t] = v; __syncthreads();
    for (int off = 1; off < 256; off <<= 1) {
        int u = (t >= off) ? sm[t - off] : 0;
        __syncthreads(); sm[t] += u; __syncthreads();
    }
    if (t < NB_SCAN) g_boff[t] = sm[t] - v;
    if (t == NB_SCAN - 1) g_rowptr[N_NODES] = sm[t];
}
__global__ void k_scan3() {
    int idx = blockIdx.x * 256 + threadIdx.x;
    if (idx < N_NODES) {
        int rp = g_boff[blockIdx.x] + g_cnt[idx];
        g_rowptr[idx] = rp; g_cursor[idx] = rp;
    }
}
__global__ void k_fill(const void* __restrict__ e) {
    int i = blockIdx.x * blockDim.x + threadIdx.x;
    if (i < N_EDGES) {
        int s = e_at(e, i);
        int d = e_at(e, (long long)N_EDGES + i);
        g_col[atomicAdd(&g_cursor[d], 1)] = s;
    }
}

// ------------------------- graph ranges via binary search ------------------
__global__ void k_graphs(const void* __restrict__ batch) {
    int g = threadIdx.x;                   // 0..127
    int lo = 0, hi = N_NODES;
    while (lo < hi) {
        int mid = (lo + hi) >> 1;
        if (b_at(batch, mid) < g) lo = mid + 1; else hi = mid;
    }
    g_gptr[g] = lo;
    if (g == 0) g_gptr[N_GRAPHS] = N_NODES;
    __syncthreads();
    int nxt = (g < N_GRAPHS - 1) ? g_gptr[g + 1] : N_NODES;
    g_gcnt[g] = fmaxf((float)(nxt - lo), 1.0f);
}

// ------------------------- aggregation: out = in + sum_{j->i} in[j] -------
// High-occupancy standalone gather: 50K warps hide L2 latency (R7 lesson:
// do NOT fuse this into the occ-limited GEMM kernel).
__global__ void __launch_bounds__(256) k_agg(const float* __restrict__ in,
                                             float* __restrict__ out) {
    int warp = (blockIdx.x * blockDim.x + threadIdx.x) >> 5;
    int lane = threadIdx.x & 31;
    if (warp >= N_NODES) return;
    int s = g_rowptr[warp], e = g_rowptr[warp + 1];
    float4 acc = ((const float4*)(in + (size_t)warp * D))[lane];
    int i = s;
    for (; i + 4 <= e; i += 4) {
        int s0 = g_col[i], s1 = g_col[i + 1], s2 = g_col[i + 2], s3 = g_col[i + 3];
        float4 v0 = __ldg(((const float4*)(in + (size_t)s0 * D)) + lane);
        float4 v1 = __ldg(((const float4*)(in + (size_t)s1 * D)) + lane);
        float4 v2 = __ldg(((const float4*)(in + (size_t)s2 * D)) + lane);
        float4 v3 = __ldg(((const float4*)(in + (size_t)s3 * D)) + lane);
        acc.x += v0.x + v1.x + v2.x + v3.x;
        acc.y += v0.y + v1.y + v2.y + v3.y;
        acc.z += v0.z + v1.z + v2.z + v3.z;
        acc.w += v0.w + v1.w + v2.w + v3.w;
    }
    for (; i < e; i++) {
        float4 v = __ldg(((const float4*)(in + (size_t)g_col[i] * D)) + lane);
        acc.x += v.x; acc.y += v.y; acc.z += v.z; acc.w += v.w;
    }
    ((float4*)(out + (size_t)warp * D))[lane] = acc;
}

// ---- fused GIN MLP: gemm1+relu+gemm2+relu+stats, 64-row M tile, occ=2 ----
// smem = As[64][PAD] + Bs[128][PAD] = ~99KB -> 2 CTAs/SM. W1 and W2 are
// staged sequentially into the same Bs buffer.
#define SMEM_GIN ((64 * PAD + 128 * PAD) * 4)

__global__ void __launch_bounds__(256) k_gin(const float* __restrict__ A,
                                             int layer,
                                             const float* __restrict__ bias1,
                                             const float* __restrict__ bias2,
                                             const void* __restrict__ batch,
                                             float* __restrict__ Hout) {
    extern __shared__ float sm[];
    float* As = sm;                  // [64][PAD]   A tile, then H1 tile
    float* Bs = sm + 64 * PAD;       // [128][PAD]  W1^T then W2^T; then H stage
    __shared__ float b1s[128], b2s[128];
    __shared__ int gids[64];

    int tid = threadIdx.x, wid = tid >> 5, lane = tid & 31;
    int warp_m = wid & 1, warp_n = wid >> 1;     // 2 x 4 warp grid, 32x32 tiles
    int gID = lane >> 2, tig = lane & 3;
    int rb = blockIdx.x * 64;
    int nvalid = min(64, N_NODES - rb);

    // stage A (tf32-rounded): 64x128 floats = 2048 float4, 8 iters
#pragma unroll
    for (int it = 0; it < 8; it++) {
        int idx = tid + it * 256;          // 0..2047
        int r = idx >> 5, c4 = (idx & 31) * 4;
        float4 v = make_float4(0.f, 0.f, 0.f, 0.f);
        if (r < nvalid) {
            v = *(const float4*)(A + (size_t)(rb + r) * D + c4);
            v.x = to_tf32(v.x); v.y = to_tf32(v.y);
            v.z = to_tf32(v.z); v.w = to_tf32(v.w);
        }
        *(float4*)(As + r * PAD + c4) = v;
    }
    // stage W1^T: 128x128 = 4096 float4, 16 iters
#pragma unroll
    for (int it = 0; it < 16; it++) {
        int idx = tid + it * 256;
        int r = idx >> 5, c4 = (idx & 31) * 4;
        *(float4*)(Bs + r * PAD + c4) = *(const float4*)(g_wT[layer] + idx * 4);
    }
    if (tid < 128) b1s[tid] = bias1[tid];
    else b2s[tid - 128] = bias2[tid - 128];
    if (tid < 64) gids[tid] = (tid < nvalid) ? b_at(batch, rb + tid) : 0;
    __syncthreads();

    float c[2][4][4];
    float a[2][4];

    // ---------------- GEMM1: H1 = relu(A @ W1 + b1) ----------------
#pragma unroll
    for (int i = 0; i < 2; i++)
#pragma unroll
        for (int j = 0; j < 4; j++)
#pragma unroll
            for (int q = 0; q < 4; q++) c[i][j][q] = 0.f;

#pragma unroll 4
    for (int kk = 0; kk < 16; kk++) {
        int k0 = kk * 8;
#pragma unroll
        for (int i = 0; i < 2; i++) {
            int row = warp_m * 32 + i * 16;
            a[i][0] = As[(row + gID) * PAD + k0 + tig];
            a[i][1] = As[(row + gID + 8) * PAD + k0 + tig];
            a[i][2] = As[(row + gID) * PAD + k0 + tig + 4];
            a[i][3] = As[(row + gID + 8) * PAD + k0 + tig + 4];
        }
#pragma unroll
        for (int j = 0; j < 4; j++) {
            int n = warp_n * 32 + j * 8 + gID;
            uint32_t b0 = __float_as_uint(Bs[n * PAD + k0 + tig]);
            uint32_t b1 = __float_as_uint(Bs[n * PAD + k0 + tig + 4]);
            mma_tf32(c[0][j], a[0], b0, b1);
            mma_tf32(c[1][j], a[1], b0, b1);
        }
    }
    __syncthreads();   // GEMM1 reads of As and Bs complete

    // write H1 (tf32) into As, stage W2^T into Bs
#pragma unroll
    for (int i = 0; i < 2; i++) {
        int r0 = warp_m * 32 + i * 16 + gID;
#pragma unroll
        for (int j = 0; j < 4; j++) {
            int cb = warp_n * 32 + j * 8 + 2 * tig;
            As[r0 * PAD + cb]       = to_tf32(fmaxf(c[i][j][0] + b1s[cb], 0.f));
            As[r0 * PAD + cb + 1]   = to_tf32(fmaxf(c[i][j][1] + b1s[cb + 1], 0.f));
            As[(r0 + 8) * PAD + cb]     = to_tf32(fmaxf(c[i][j][2] + b1s[cb], 0.f));
            As[(r0 + 8) * PAD + cb + 1] = to_tf32(fmaxf(c[i][j][3] + b1s[cb + 1], 0.f));
        }
    }
#pragma unroll
    for (int it = 0; it < 16; it++) {
        int idx = tid + it * 256;
        int r = idx >> 5, c4 = (idx & 31) * 4;
        *(float4*)(Bs + r * PAD + c4) = *(const float4*)(g_wT[4 + layer] + idx * 4);
    }
    __syncthreads();

    // ---------------- GEMM2: H = relu(H1 @ W2 + b2) ----------------
#pragma unroll
    for (int i = 0; i < 2; i++)
#pragma unroll
        for (int j = 0; j < 4; j++)
#pragma unroll
            for (int q = 0; q < 4; q++) c[i][j][q] = 0.f;

#pragma unroll 4
    for (int kk = 0; kk < 16; kk++) {
        int k0 = kk * 8;
#pragma unroll
        for (int i = 0; i < 2; i++) {
            int row = warp_m * 32 + i * 16;
            a[i][0] = As[(row + gID) * PAD + k0 + tig];
            a[i][1] = As[(row + gID + 8) * PAD + k0 + tig];
            a[i][2] = As[(row + gID) * PAD + k0 + tig + 4];
            a[i][3] = As[(row + gID + 8) * PAD + k0 + tig + 4];
        }
#pragma unroll
        for (int j = 0; j < 4; j++) {
            int n = warp_n * 32 + j * 8 + gID;
            uint32_t b0 = __float_as_uint(Bs[n * PAD + k0 + tig]);
            uint32_t b1 = __float_as_uint(Bs[n * PAD + k0 + tig + 4]);
            mma_tf32(c[0][j], a[0], b0, b1);
            mma_tf32(c[1][j], a[1], b0, b1);
        }
    }
    __syncthreads();   // GEMM2 reads of Bs complete (before H staging reuse)

    // epilogue: H -> global + smem staging (reuse Bs[0:64][PAD])
    float* Hs = Bs;
#pragma unroll
    for (int i = 0; i < 2; i++) {
        int lr0 = warp_m * 32 + i * 16 + gID;
        int lr1 = lr0 + 8;
#pragma unroll
        for (int j = 0; j < 4; j++) {
            int cb = warp_n * 32 + j * 8 + 2 * tig;
            float2 o0, o1;
            o0.x = fmaxf(c[i][j][0] + b2s[cb], 0.f);
            o0.y = fmaxf(c[i][j][1] + b2s[cb + 1], 0.f);
            o1.x = fmaxf(c[i][j][2] + b2s[cb], 0.f);
            o1.y = fmaxf(c[i][j][3] + b2s[cb + 1], 0.f);
            Hs[lr0 * PAD + cb] = o0.x;  Hs[lr0 * PAD + cb + 1] = o0.y;
            Hs[lr1 * PAD + cb] = o1.x;  Hs[lr1 * PAD + cb + 1] = o1.y;
            if (lr0 < nvalid) *(float2*)(Hout + (size_t)(rb + lr0) * D + cb) = o0;
            if (lr1 < nvalid) *(float2*)(Hout + (size_t)(rb + lr1) * D + cb) = o1;
        }
    }
    __syncthreads();

    // per-graph stats (sum, sumsq) from smem, 2 strips of 32 rows
    {
        int d = tid & 127, half = tid >> 7;
        int r0 = half * 32, r1 = min(r0 + 32, nvalid);
        if (r0 < nvalid) {
            int curg = gids[r0];
            float s = 0.f, q = 0.f;
            for (int r = r0; r < r1; r++) {
                int g = gids[r];
                if (g != curg) {
                    atomicAdd(&g_stat[layer][curg][0][d], s);
                    atomicAdd(&g_stat[layer][curg][1][d], q);
                    s = 0.f; q = 0.f; curg = g;
                }
                float v = Hs[r * PAD + d];
                s += v; q += v * v;
            }
            atomicAdd(&g_stat[layer][curg][0][d], s);
            atomicAdd(&g_stat[layer][curg][1][d], q);
        }
    }
}

// ------------------------- GraphNorm apply + relu (+pool on last) ----------
// In-place on g_h (row-wise, no cross-row deps).
__global__ void __launch_bounds__(256) k_gnapply(const void* __restrict__ batch,
                                                 const float* __restrict__ w,
                                                 const float* __restrict__ b,
                                                 const float* __restrict__ ms,
                                                 int layer, int last) {
    int warp = (blockIdx.x * blockDim.x + threadIdx.x) >> 5;
    int lane = threadIdx.x & 31;
    if (warp >= N_NODES) return;
    int g = b_at(batch, warp);
    float c = g_gcnt[g];
    int d0 = lane * 4;
    float4 h  = ((const float4*)(g_h + (size_t)warp * D))[lane];
    float4 s4 = *(const float4*)&g_stat[layer][g][0][d0];
    float4 q4 = *(const float4*)&g_stat[layer][g][1][d0];
    float4 ms4 = *(const float4*)(ms + layer * D + d0);
    float4 w4  = *(const float4*)(w  + layer * D + d0);
    float4 b4  = *(const float4*)(b  + layer * D + d0);
    float4 o;
#define GN1(X) {                                                   \
    float mean = s4.X / c;                                         \
    float aa = mean * ms4.X;                                       \
    float var = q4.X / c - 2.f * aa * mean + aa * aa;              \
    float rstd = rsqrtf(var + GN_EPS);                             \
    o.X = fmaxf(w4.X * (h.X - aa) * rstd + b4.X, 0.f); }
    GN1(x) GN1(y) GN1(z) GN1(w)
#undef GN1
    if (last) {
        atomicAdd(&g_pool[g * D + d0 + 0], o.x);
        atomicAdd(&g_pool[g * D + d0 + 1], o.y);
        atomicAdd(&g_pool[g * D + d0 + 2], o.z);
        atomicAdd(&g_pool[g * D + d0 + 3], o.w);
    } else {
        ((float4*)(g_h + (size_t)warp * D))[lane] = o;
    }
}

// ------------------------- final MLP + log_softmax -------------------------
__global__ void __launch_bounds__(128) k_mlp(const float* __restrict__ fw1,
                                             const float* __restrict__ fb1,
                                             const float* __restrict__ fw2,
                                             const float* __restrict__ fb2,
                                             const float* __restrict__ fw3,
                                             const float* __restrict__ fb3,
                                             float* __restrict__ out) {
    int g = blockIdx.x, t = threadIdx.x;
    __shared__ float v[D], v2[D], o[C], red[2];
    v[t] = g_pool[g * D + t];
    __syncthreads();
    float acc = fb1[t];
    for (int k = 0; k < D; k++) acc += v[k] * fw1[k * D + t];
    v2[t] = fmaxf(acc, 0.f);
    __syncthreads();
    acc = fb2[t];
    for (int k = 0; k < D; k++) acc += v2[k] * fw2[k * D + t];
    __syncthreads();
    v[t] = fmaxf(acc, 0.f);
    __syncthreads();
    if (t < C) {
        float a = fb3[t];
        for (int k = 0; k < D; k++) a += v[k] * fw3[k * C + t];
        o[t] = a;
    }
    __syncthreads();
    if (t == 0) {
        float m = -1e30f;
        for (int cc = 0; cc < C; cc++) m = fmaxf(m, o[cc]);
        float se = 0.f;
        for (int cc = 0; cc < C; cc++) se += expf(o[cc] - m);
        red[0] = m; red[1] = logf(se);
    }
    __syncthreads();
    if (t < C) out[g * C + t] = o[t] - red[0] - red[1];
}

// ------------------------- launcher ----------------------------------------
extern "C" void kernel_launch(void* const* d_in, const int* in_sizes, int n_in,
                              void* d_out, int out_size) {
    const float* x    = (const float*)d_in[0];
    const float* w1   = (const float*)d_in[1];
    const float* b1   = (const float*)d_in[2];
    const float* w2   = (const float*)d_in[3];
    const float* b2   = (const float*)d_in[4];
    const float* gnw  = (const float*)d_in[5];
    const float* gnb  = (const float*)d_in[6];
    const float* gns  = (const float*)d_in[7];
    const float* fw1  = (const float*)d_in[8];
    const float* fb1  = (const float*)d_in[9];
    const float* fw2  = (const float*)d_in[10];
    const float* fb2  = (const float*)d_in[11];
    const float* fw3  = (const float*)d_in[12];
    const float* fb3  = (const float*)d_in[13];
    const void*  edge  = d_in[14];
    const void*  batch = d_in[15];
    float* out = (float*)d_out;

    float *p_h, *p_a;
    cudaGetSymbolAddress((void**)&p_h, g_h);
    cudaGetSymbolAddress((void**)&p_a, g_a);
    cudaFuncSetAttribute(k_gin, cudaFuncAttributeMaxDynamicSharedMemorySize,
                         SMEM_GIN);

    // prologue
    k_prep<<<(ZERO_ELEMS + 255) / 256, 256>>>((const int*)edge, (const int*)batch);
    k_wt<<<8, 256>>>(w1, w2);
    k_hist<<<(N_EDGES + 255) / 256, 256>>>(edge);
    k_scan1<<<NB_SCAN, 256>>>();
    k_scan2<<<1, 256>>>();
    k_scan3<<<NB_SCAN, 256>>>();
    k_fill<<<(N_EDGES + 255) / 256, 256>>>(edge);
    k_graphs<<<1, N_GRAPHS>>>(batch);

    const int ginGrid = (N_NODES + 63) / 64;          // 782
    const int aggGrid = (N_NODES * 32 + 255) / 256;   // 6250

    for (int l = 0; l < L; l++) {
        const float* hin = (l == 0) ? x : p_h;
        k_agg<<<aggGrid, 256>>>(hin, p_a);                    // read h, write a
        k_gin<<<ginGrid, 256, SMEM_GIN>>>(p_a, l,             // read a, write h
                                          b1 + (size_t)l * D, b2 + (size_t)l * D,
                                          batch, p_h);
        k_gnapply<<<aggGrid, 256>>>(batch, gnw, gnb, gns, l, l == L - 1);
    }
    k_mlp<<<N_GRAPHS, 128>>>(fw1, fb1, fw2, fb2, fw3, fb3, out);
}

// round 9
// speedup vs baseline: 1.3947x; 1.0244x over previous
#include <cuda_runtime.h>
#include <cuda_fp16.h>
#include <cstdint>

#define N_NODES 50000
#define N_EDGES 800000
#define N_GRAPHS 128
#define D 128
#define L 4
#define C 10
#define GN_EPS 1e-5f
#define NB_SCAN 196
#define PAD 132
#define ZERO_ELEMS (L * N_GRAPHS * 2 * D)   // 131072, largest scratch to clear

// ------------------------- device scratch (static, no allocs) -------------
__device__ float  g_h[(size_t)N_NODES * D];   // un-normalized H (gin out)
__device__ float  g_a[(size_t)N_NODES * D];   // agg output / gin input
__device__ __half g_hh[(size_t)N_NODES * D];  // fp16 mirror of normalized state
__device__ int    g_rowptr[N_NODES + 1];
__device__ int    g_cursor[N_NODES];
__device__ int    g_cnt[N_NODES];
__device__ int    g_col[N_EDGES];
__device__ int    g_bsum[NB_SCAN];
__device__ int    g_boff[NB_SCAN];
__device__ int    g_gptr[N_GRAPHS + 1];
__device__ float  g_gcnt[N_GRAPHS];
__device__ float  g_pool[N_GRAPHS * D];
__device__ float  g_stat[L][N_GRAPHS][2][D];    // [l][g][{sum,sumsq}][d]
__device__ float  g_wT[8][16384];               // W^T (tf32-rounded), B[n][k]
__device__ int    g_is64e;
__device__ int    g_is64b;

// ------------------------- helpers ----------------------------------------
__device__ __forceinline__ int e_at(const void* p, long long i) {
    if (g_is64e) return (int)((const long long*)p)[i];
    return ((const int*)p)[i];
}
__device__ __forceinline__ int b_at(const void* p, long long i) {
    if (g_is64b) return (int)((const long long*)p)[i];
    return ((const int*)p)[i];
}
__device__ __forceinline__ float to_tf32(float x) {
    float r; asm("cvt.rna.tf32.f32 %0, %1;" : "=f"(r) : "f"(x)); return r;
}

// mma.sync m16n8k8 tf32: D = A*B + D
__device__ __forceinline__ void mma_tf32(float c[4], const float a[4],
                                         uint32_t b0, uint32_t b1) {
    const uint32_t* A = reinterpret_cast<const uint32_t*>(a);
    asm volatile(
        "mma.sync.aligned.m16n8k8.row.col.f32.tf32.tf32.f32 "
        "{%0,%1,%2,%3}, {%4,%5,%6,%7}, {%8,%9}, {%0,%1,%2,%3};"
        : "+f"(c[0]), "+f"(c[1]), "+f"(c[2]), "+f"(c[3])
        : "r"(A[0]), "r"(A[1]), "r"(A[2]), "r"(A[3]), "r"(b0), "r"(b1));
}

// unpack 8 bytes (4 halfs) -> float4 accumulate
__device__ __forceinline__ void acc_h4(float4& acc, uint2 r) {
    float2 f0 = __half22float2(*reinterpret_cast<__half2*>(&r.x));
    float2 f1 = __half22float2(*reinterpret_cast<__half2*>(&r.y));
    acc.x += f0.x; acc.y += f0.y; acc.z += f1.x; acc.w += f1.y;
}

// ------------------------- prep: zero scratch + dtype detect ---------------
__global__ void k_prep(const int* __restrict__ ew, const int* __restrict__ bw) {
    int i = blockIdx.x * blockDim.x + threadIdx.x;
    if (i < N_NODES) g_cnt[i] = 0;
    if (i < ZERO_ELEMS) (&g_stat[0][0][0][0])[i] = 0.f;
    if (i < N_GRAPHS * D) g_pool[i] = 0.f;
    if (blockIdx.x == 0) {
        __shared__ int s_ez, s_bg;
        if (threadIdx.x == 0) { s_ez = 1; s_bg = 0; }
        __syncthreads();
        for (int j = threadIdx.x; j < 128; j += blockDim.x)
            if (ew[2 * j + 1] != 0) atomicAnd(&s_ez, 0);
        for (int j = threadIdx.x; j < 24999; j += blockDim.x)
            if (bw[2 * j] > bw[2 * j + 1]) atomicOr(&s_bg, 1);
        __syncthreads();
        if (threadIdx.x == 0) { g_is64e = s_ez; g_is64b = s_bg; }
    }
}

// ------------------------- x -> fp16 mirror --------------------------------
__global__ void k_x2h(const float* __restrict__ x) {
    int i = blockIdx.x * blockDim.x + threadIdx.x;      // over N*D/4
    if (i < N_NODES * D / 4) {
        float4 v = *(const float4*)(x + (size_t)i * 4);
        __half2 h0 = __floats2half2_rn(v.x, v.y);
        __half2 h1 = __floats2half2_rn(v.z, v.w);
        uint2 pk;
        pk.x = *reinterpret_cast<uint32_t*>(&h0);
        pk.y = *reinterpret_cast<uint32_t*>(&h1);
        ((uint2*)g_hh)[i] = pk;
    }
}

// ------------------------- weight transpose (tf32-rounded) -----------------
__global__ void k_wt(const float* __restrict__ w1, const float* __restrict__ w2) {
    int m = blockIdx.x;                     // 0..7
    const float* W = (m < 4) ? (w1 + (size_t)m * D * D) : (w2 + (size_t)(m - 4) * D * D);
    for (int idx = threadIdx.x; idx < D * D; idx += blockDim.x) {
        int k = idx >> 7, n = idx & 127;
        g_wT[m][n * D + k] = to_tf32(W[idx]);   // B[n][k] = W[k][n]
    }
}

// ------------------------- CSR build ---------------------------------------
__global__ void k_hist(const void* __restrict__ e) {
    int i = blockIdx.x * blockDim.x + threadIdx.x;
    if (i < N_EDGES) atomicAdd(&g_cnt[e_at(e, (long long)N_EDGES + i)], 1);
}
__global__ void k_scan1() {
    __shared__ int sm[256];
    int t = threadIdx.x, idx = blockIdx.x * 256 + t;
    int v = (idx < N_NODES) ? g_cnt[idx] : 0;
    sm[t] = v; __syncthreads();
    for (int off = 1; off < 256; off <<= 1) {
        int u = (t >= off) ? sm[t - off] : 0;
        __syncthreads(); sm[t] += u; __syncthreads();
    }
    if (idx < N_NODES) g_cnt[idx] = sm[t] - v;
    if (t == 255) g_bsum[blockIdx.x] = sm[255];
}
__global__ void k_scan2() {
    __shared__ int sm[256];
    int t = threadIdx.x;
    int v = (t < NB_SCAN) ? g_bsum[t] : 0;
    sm[t] = v; __syncthreads();
    for (int off = 1; off < 256; off <<= 1) {
        int u = (t >= off) ? sm[t - off] : 0;
        __syncthreads(); sm[t] += u; __syncthreads();
    }
    if (t < NB_SCAN) g_boff[t] = sm[t] - v;
    if (t == NB_SCAN - 1) g_rowptr[N_NODES] = sm[t];
}
__global__ void k_scan3() {
    int idx = blockIdx.x * 256 + threadIdx.x;
    if (idx < N_NODES) {
        int rp = g_boff[blockIdx.x] + g_cnt[idx];
        g_rowptr[idx] = rp; g_cursor[idx] = rp;
    }
}
__global__ void k_fill(const void* __restrict__ e) {
    int i = blockIdx.x * blockDim.x + threadIdx.x;
    if (i < N_EDGES) {
        int s = e_at(e, i);
        int d = e_at(e, (long long)N_EDGES + i);
        g_col[atomicAdd(&g_cursor[d], 1)] = s;
    }
}

// ------------------------- graph ranges via binary search ------------------
__global__ void k_graphs(const void* __restrict__ batch) {
    int g = threadIdx.x;                   // 0..127
    int lo = 0, hi = N_NODES;
    while (lo < hi) {
        int mid = (lo + hi) >> 1;
        if (b_at(batch, mid) < g) lo = mid + 1; else hi = mid;
    }
    g_gptr[g] = lo;
    if (g == 0) g_gptr[N_GRAPHS] = N_NODES;
    __syncthreads();
    int nxt = (g < N_GRAPHS - 1) ? g_gptr[g + 1] : N_NODES;
    g_gcnt[g] = fmaxf((float)(nxt - lo), 1.0f);
}

// ------------------------- aggregation (fp16 gather, fp32 accum) ----------
// out[i] = hh[i] + sum_{j->i} hh[j]. 8B/lane/row = 256B/row: half the L2
// traffic of the fp32 version. High occupancy (50K warps) hides L2 latency.
__global__ void __launch_bounds__(256) k_agg(float* __restrict__ out) {
    int warp = (blockIdx.x * blockDim.x + threadIdx.x) >> 5;
    int lane = threadIdx.x & 31;
    if (warp >= N_NODES) return;
    int s = g_rowptr[warp], e = g_rowptr[warp + 1];
    float4 acc = make_float4(0.f, 0.f, 0.f, 0.f);
    acc_h4(acc, __ldg(((const uint2*)(g_hh + (size_t)warp * D)) + lane));
    int i = s;
    for (; i + 4 <= e; i += 4) {
        int s0 = g_col[i], s1 = g_col[i + 1], s2 = g_col[i + 2], s3 = g_col[i + 3];
        uint2 r0 = __ldg(((const uint2*)(g_hh + (size_t)s0 * D)) + lane);
        uint2 r1 = __ldg(((const uint2*)(g_hh + (size_t)s1 * D)) + lane);
        uint2 r2 = __ldg(((const uint2*)(g_hh + (size_t)s2 * D)) + lane);
        uint2 r3 = __ldg(((const uint2*)(g_hh + (size_t)s3 * D)) + lane);
        acc_h4(acc, r0); acc_h4(acc, r1); acc_h4(acc, r2); acc_h4(acc, r3);
    }
    for (; i < e; i++)
        acc_h4(acc, __ldg(((const uint2*)(g_hh + (size_t)g_col[i] * D)) + lane));
    ((float4*)(out + (size_t)warp * D))[lane] = acc;
}

// ---- fused GIN MLP: gemm1+relu+gemm2+relu+stats, 64-row M tile, occ=2 ----
#define SMEM_GIN ((64 * PAD + 128 * PAD) * 4)

__global__ void __launch_bounds__(256) k_gin(const float* __restrict__ A,
                                             int layer,
                                             const float* __restrict__ bias1,
                                             const float* __restrict__ bias2,
                                             const void* __restrict__ batch,
                                             float* __restrict__ Hout) {
    extern __shared__ float sm[];
    float* As = sm;                  // [64][PAD]   A tile, then H1 tile
    float* Bs = sm + 64 * PAD;       // [128][PAD]  W1^T then W2^T; then H stage
    __shared__ float b1s[128], b2s[128];
    __shared__ int gids[64];

    int tid = threadIdx.x, wid = tid >> 5, lane = tid & 31;
    int warp_m = wid & 1, warp_n = wid >> 1;     // 2 x 4 warp grid, 32x32 tiles
    int gID = lane >> 2, tig = lane & 3;
    int rb = blockIdx.x * 64;
    int nvalid = min(64, N_NODES - rb);

    // stage A (tf32-rounded)
#pragma unroll
    for (int it = 0; it < 8; it++) {
        int idx = tid + it * 256;          // 0..2047
        int r = idx >> 5, c4 = (idx & 31) * 4;
        float4 v = make_float4(0.f, 0.f, 0.f, 0.f);
        if (r < nvalid) {
            v = *(const float4*)(A + (size_t)(rb + r) * D + c4);
            v.x = to_tf32(v.x); v.y = to_tf32(v.y);
            v.z = to_tf32(v.z); v.w = to_tf32(v.w);
        }
        *(float4*)(As + r * PAD + c4) = v;
    }
#pragma unroll
    for (int it = 0; it < 16; it++) {       // W1^T
        int idx = tid + it * 256;
        int r = idx >> 5, c4 = (idx & 31) * 4;
        *(float4*)(Bs + r * PAD + c4) = *(const float4*)(g_wT[layer] + idx * 4);
    }
    if (tid < 128) b1s[tid] = bias1[tid];
    else b2s[tid - 128] = bias2[tid - 128];
    if (tid < 64) gids[tid] = (tid < nvalid) ? b_at(batch, rb + tid) : 0;
    __syncthreads();

    float c[2][4][4];
    float a[2][4];

    // ---------------- GEMM1 ----------------
#pragma unroll
    for (int i = 0; i < 2; i++)
#pragma unroll
        for (int j = 0; j < 4; j++)
#pragma unroll
            for (int q = 0; q < 4; q++) c[i][j][q] = 0.f;

#pragma unroll 4
    for (int kk = 0; kk < 16; kk++) {
        int k0 = kk * 8;
#pragma unroll
        for (int i = 0; i < 2; i++) {
            int row = warp_m * 32 + i * 16;
            a[i][0] = As[(row + gID) * PAD + k0 + tig];
            a[i][1] = As[(row + gID + 8) * PAD + k0 + tig];
            a[i][2] = As[(row + gID) * PAD + k0 + tig + 4];
            a[i][3] = As[(row + gID + 8) * PAD + k0 + tig + 4];
        }
#pragma unroll
        for (int j = 0; j < 4; j++) {
            int n = warp_n * 32 + j * 8 + gID;
            uint32_t b0 = __float_as_uint(Bs[n * PAD + k0 + tig]);
            uint32_t b1 = __float_as_uint(Bs[n * PAD + k0 + tig + 4]);
            mma_tf32(c[0][j], a[0], b0, b1);
            mma_tf32(c[1][j], a[1], b0, b1);
        }
    }
    __syncthreads();

    // H1 -> As, stage W2^T -> Bs
#pragma unroll
    for (int i = 0; i < 2; i++) {
        int r0 = warp_m * 32 + i * 16 + gID;
#pragma unroll
        for (int j = 0; j < 4; j++) {
            int cb = warp_n * 32 + j * 8 + 2 * tig;
            As[r0 * PAD + cb]       = to_tf32(fmaxf(c[i][j][0] + b1s[cb], 0.f));
            As[r0 * PAD + cb + 1]   = to_tf32(fmaxf(c[i][j][1] + b1s[cb + 1], 0.f));
            As[(r0 + 8) * PAD + cb]     = to_tf32(fmaxf(c[i][j][2] + b1s[cb], 0.f));
            As[(r0 + 8) * PAD + cb + 1] = to_tf32(fmaxf(c[i][j][3] + b1s[cb + 1], 0.f));
        }
    }
#pragma unroll
    for (int it = 0; it < 16; it++) {
        int idx = tid + it * 256;
        int r = idx >> 5, c4 = (idx & 31) * 4;
        *(float4*)(Bs + r * PAD + c4) = *(const float4*)(g_wT[4 + layer] + idx * 4);
    }
    __syncthreads();

    // ---------------- GEMM2 ----------------
#pragma unroll
    for (int i = 0; i < 2; i++)
#pragma unroll
        for (int j = 0; j < 4; j++)
#pragma unroll
            for (int q = 0; q < 4; q++) c[i][j][q] = 0.f;

#pragma unroll 4
    for (int kk = 0; kk < 16; kk++) {
        int k0 = kk * 8;
#pragma unroll
        for (int i = 0; i < 2; i++) {
            int row = warp_m * 32 + i * 16;
            a[i][0] = As[(row + gID) * PAD + k0 + tig];
            a[i][1] = As[(row + gID + 8) * PAD + k0 + tig];
            a[i][2] = As[(row + gID) * PAD + k0 + tig + 4];
            a[i][3] = As[(row + gID + 8) * PAD + k0 + tig + 4];
        }
#pragma unroll
        for (int j = 0; j < 4; j++) {
            int n = warp_n * 32 + j * 8 + gID;
            uint32_t b0 = __float_as_uint(Bs[n * PAD + k0 + tig]);
            uint32_t b1 = __float_as_uint(Bs[n * PAD + k0 + tig + 4]);
            mma_tf32(c[0][j], a[0], b0, b1);
            mma_tf32(c[1][j], a[1], b0, b1);
        }
    }
    __syncthreads();

    // epilogue: H -> global + smem staging (reuse Bs rows 0..63)
    float* Hs = Bs;
#pragma unroll
    for (int i = 0; i < 2; i++) {
        int lr0 = warp_m * 32 + i * 16 + gID;
        int lr1 = lr0 + 8;
#pragma unroll
        for (int j = 0; j < 4; j++) {
            int cb = warp_n * 32 + j * 8 + 2 * tig;
            float2 o0, o1;
            o0.x = fmaxf(c[i][j][0] + b2s[cb], 0.f);
            o0.y = fmaxf(c[i][j][1] + b2s[cb + 1], 0.f);
            o1.x = fmaxf(c[i][j][2] + b2s[cb], 0.f);
            o1.y = fmaxf(c[i][j][3] + b2s[cb + 1], 0.f);
            Hs[lr0 * PAD + cb] = o0.x;  Hs[lr0 * PAD + cb + 1] = o0.y;
            Hs[lr1 * PAD + cb] = o1.x;  Hs[lr1 * PAD + cb + 1] = o1.y;
            if (lr0 < nvalid) *(float2*)(Hout + (size_t)(rb + lr0) * D + cb) = o0;
            if (lr1 < nvalid) *(float2*)(Hout + (size_t)(rb + lr1) * D + cb) = o1;
        }
    }
    __syncthreads();

    // per-graph stats (sum, sumsq) from smem, 2 strips of 32 rows
    {
        int d = tid & 127, half = tid >> 7;
        int r0 = half * 32, r1 = min(r0 + 32, nvalid);
        if (r0 < nvalid) {
            int curg = gids[r0];
            float s = 0.f, q = 0.f;
            for (int r = r0; r < r1; r++) {
                int g = gids[r];
                if (g != curg) {
                    atomicAdd(&g_stat[layer][curg][0][d], s);
                    atomicAdd(&g_stat[layer][curg][1][d], q);
                    s = 0.f; q = 0.f; curg = g;
                }
                float v = Hs[r * PAD + d];
                s += v; q += v * v;
            }
            atomicAdd(&g_stat[layer][curg][0][d], s);
            atomicAdd(&g_stat[layer][curg][1][d], q);
        }
    }
}

// ------------------------- GraphNorm apply + relu --------------------------
// Reads g_h (fp32 gin out), writes fp16 mirror g_hh (next agg's input) or
// pool on the last layer.
__global__ void __launch_bounds__(256) k_gnapply(const void* __restrict__ batch,
                                                 const float* __restrict__ w,
                                                 const float* __restrict__ b,
                                                 const float* __restrict__ ms,
                                                 int layer, int last) {
    int warp = (blockIdx.x * blockDim.x + threadIdx.x) >> 5;
    int lane = threadIdx.x & 31;
    if (warp >= N_NODES) return;
    int g = b_at(batch, warp);
    float c = g_gcnt[g];
    int d0 = lane * 4;
    float4 h  = ((const float4*)(g_h + (size_t)warp * D))[lane];
    float4 s4 = *(const float4*)&g_stat[layer][g][0][d0];
    float4 q4 = *(const float4*)&g_stat[layer][g][1][d0];
    float4 ms4 = *(const float4*)(ms + layer * D + d0);
    float4 w4  = *(const float4*)(w  + layer * D + d0);
    float4 b4  = *(const float4*)(b  + layer * D + d0);
    float4 o;
#define GN1(X) {                                                   \
    float mean = s4.X / c;                                         \
    float aa = mean * ms4.X;                                       \
    float var = q4.X / c - 2.f * aa * mean + aa * aa;              \
    float rstd = rsqrtf(var + GN_EPS);                             \
    o.X = fmaxf(w4.X * (h.X - aa) * rstd + b4.X, 0.f); }
    GN1(x) GN1(y) GN1(z) GN1(w)
#undef GN1
    if (last) {
        atomicAdd(&g_pool[g * D + d0 + 0], o.x);
        atomicAdd(&g_pool[g * D + d0 + 1], o.y);
        atomicAdd(&g_pool[g * D + d0 + 2], o.z);
        atomicAdd(&g_pool[g * D + d0 + 3], o.w);
    } else {
        __half2 h0 = __floats2half2_rn(o.x, o.y);
        __half2 h1 = __floats2half2_rn(o.z, o.w);
        uint2 pk;
        pk.x = *reinterpret_cast<uint32_t*>(&h0);
        pk.y = *reinterpret_cast<uint32_t*>(&h1);
        ((uint2*)(g_hh + (size_t)warp * D))[lane] = pk;
    }
}

// ------------------------- final MLP + log_softmax -------------------------
__global__ void __launch_bounds__(128) k_mlp(const float* __restrict__ fw1,
                                             const float* __restrict__ fb1,
                                             const float* __restrict__ fw2,
                                             const float* __restrict__ fb2,
                                             const float* __restrict__ fw3,
                                             const float* __restrict__ fb3,
                                             float* __restrict__ out) {
    int g = blockIdx.x, t = threadIdx.x;
    __shared__ float v[D], v2[D], o[C], red[2];
    v[t] = g_pool[g * D + t];
    __syncthreads();
    float acc = fb1[t];
    for (int k = 0; k < D; k++) acc += v[k] * fw1[k * D + t];
    v2[t] = fmaxf(acc, 0.f);
    __syncthreads();
    acc = fb2[t];
    for (int k = 0; k < D; k++) acc += v2[k] * fw2[k * D + t];
    __syncthreads();
    v[t] = fmaxf(acc, 0.f);
    __syncthreads();
    if (t < C) {
        float a = fb3[t];
        for (int k = 0; k < D; k++) a += v[k] * fw3[k * C + t];
        o[t] = a;
    }
    __syncthreads();
    if (t == 0) {
        float m = -1e30f;
        for (int cc = 0; cc < C; cc++) m = fmaxf(m, o[cc]);
        float se = 0.f;
        for (int cc = 0; cc < C; cc++) se += expf(o[cc] - m);
        red[0] = m; red[1] = logf(se);
    }
    __syncthreads();
    if (t < C) out[g * C + t] = o[t] - red[0] - red[1];
}

// ------------------------- launcher ----------------------------------------
extern "C" void kernel_launch(void* const* d_in, const int* in_sizes, int n_in,
                              void* d_out, int out_size) {
    const float* x    = (const float*)d_in[0];
    const float* w1   = (const float*)d_in[1];
    const float* b1   = (const float*)d_in[2];
    const float* w2   = (const float*)d_in[3];
    const float* b2   = (const float*)d_in[4];
    const float* gnw  = (const float*)d_in[5];
    const float* gnb  = (const float*)d_in[6];
    const float* gns  = (const float*)d_in[7];
    const float* fw1  = (const float*)d_in[8];
    const float* fb1  = (const float*)d_in[9];
    const float* fw2  = (const float*)d_in[10];
    const float* fb2  = (const float*)d_in[11];
    const float* fw3  = (const float*)d_in[12];
    const float* fb3  = (const float*)d_in[13];
    const void*  edge  = d_in[14];
    const void*  batch = d_in[15];
    float* out = (float*)d_out;

    float *p_h, *p_a;
    cudaGetSymbolAddress((void**)&p_h, g_h);
    cudaGetSymbolAddress((void**)&p_a, g_a);
    cudaFuncSetAttribute(k_gin, cudaFuncAttributeMaxDynamicSharedMemorySize,
                         SMEM_GIN);

    // prologue
    k_prep<<<(ZERO_ELEMS + 255) / 256, 256>>>((const int*)edge, (const int*)batch);
    k_wt<<<8, 256>>>(w1, w2);
    k_x2h<<<(N_NODES * D / 4 + 255) / 256, 256>>>(x);
    k_hist<<<(N_EDGES + 255) / 256, 256>>>(edge);
    k_scan1<<<NB_SCAN, 256>>>();
    k_scan2<<<1, 256>>>();
    k_scan3<<<NB_SCAN, 256>>>();
    k_fill<<<(N_EDGES + 255) / 256, 256>>>(edge);
    k_graphs<<<1, N_GRAPHS>>>(batch);

    const int ginGrid = (N_NODES + 63) / 64;          // 782
    const int aggGrid = (N_NODES * 32 + 255) / 256;   // 6250

    for (int l = 0; l < L; l++) {
        k_agg<<<aggGrid, 256>>>(p_a);                         // read hh, write a
        k_gin<<<ginGrid, 256, SMEM_GIN>>>(p_a, l,             // read a, write h
                                          b1 + (size_t)l * D, b2 + (size_t)l * D,
                                          batch, p_h);
        k_gnapply<<<aggGrid, 256>>>(batch, gnw, gnb, gns, l, l == L - 1);
    }
    k_mlp<<<N_GRAPHS, 128>>>(fw1, fb1, fw2, fb2, fw3, fb3, out);
}

// round 10
// speedup vs baseline: 1.5847x; 1.1363x over previous
#include <cuda_runtime.h>
#include <cuda_fp16.h>
#include <cstdint>

#define N_NODES 50000
#define N_EDGES 800000
#define N_GRAPHS 128
#define D 128
#define L 4
#define C 10
#define GN_EPS 1e-5f
#define NB_SCAN 196
#define PAD 132          // float padding (stats staging)
#define PADH 136         // half padding (GEMM tiles), 68 words/row
#define ZERO_ELEMS (L * N_GRAPHS * 2 * D)

// ------------------------- device scratch (static, no allocs) -------------
__device__ float  g_h[(size_t)N_NODES * D];   // un-normalized H (gin out)
__device__ __half g_ah[(size_t)N_NODES * D];  // agg output (fp16, gin input)
__device__ __half g_hh[(size_t)N_NODES * D];  // fp16 mirror of normalized state
__device__ int    g_rowptr[N_NODES + 1];
__device__ int    g_cursor[N_NODES];
__device__ int    g_cnt[N_NODES];
__device__ int    g_col[N_EDGES];
__device__ int    g_bsum[NB_SCAN];
__device__ int    g_boff[NB_SCAN];
__device__ int    g_gptr[N_GRAPHS + 1];
__device__ float  g_gcnt[N_GRAPHS];
__device__ float  g_pool[N_GRAPHS * D];
__device__ float  g_stat[L][N_GRAPHS][2][D];
__device__ __half g_wTh[8][16384];            // W^T fp16, B[n][k]
__device__ int    g_is64e;
__device__ int    g_is64b;

// ------------------------- helpers ----------------------------------------
__device__ __forceinline__ int e_at(const void* p, long long i) {
    if (g_is64e) return (int)((const long long*)p)[i];
    return ((const int*)p)[i];
}
__device__ __forceinline__ int b_at(const void* p, long long i) {
    if (g_is64b) return (int)((const long long*)p)[i];
    return ((const int*)p)[i];
}

// mma.sync m16n8k16 fp16 (fp32 accum): C += A*B
__device__ __forceinline__ void mma_f16(float c[4], uint32_t a0, uint32_t a1,
                                        uint32_t a2, uint32_t a3,
                                        uint32_t b0, uint32_t b1) {
    asm volatile(
        "mma.sync.aligned.m16n8k16.row.col.f32.f16.f16.f32 "
        "{%0,%1,%2,%3}, {%4,%5,%6,%7}, {%8,%9}, {%0,%1,%2,%3};"
        : "+f"(c[0]), "+f"(c[1]), "+f"(c[2]), "+f"(c[3])
        : "r"(a0), "r"(a1), "r"(a2), "r"(a3), "r"(b0), "r"(b1));
}

__device__ __forceinline__ void acc_h4(float4& acc, uint2 r) {
    float2 f0 = __half22float2(*reinterpret_cast<__half2*>(&r.x));
    float2 f1 = __half22float2(*reinterpret_cast<__half2*>(&r.y));
    acc.x += f0.x; acc.y += f0.y; acc.z += f1.x; acc.w += f1.y;
}
__device__ __forceinline__ uint32_t pack_h2(float x, float y) {
    __half2 h = __floats2half2_rn(x, y);
    return *reinterpret_cast<uint32_t*>(&h);
}

// ------------------------- prep: zero scratch + dtype detect ---------------
__global__ void k_prep(const int* __restrict__ ew, const int* __restrict__ bw) {
    int i = blockIdx.x * blockDim.x + threadIdx.x;
    if (i < N_NODES) g_cnt[i] = 0;
    if (i < ZERO_ELEMS) (&g_stat[0][0][0][0])[i] = 0.f;
    if (i < N_GRAPHS * D) g_pool[i] = 0.f;
    if (blockIdx.x == 0) {
        __shared__ int s_ez, s_bg;
        if (threadIdx.x == 0) { s_ez = 1; s_bg = 0; }
        __syncthreads();
        for (int j = threadIdx.x; j < 128; j += blockDim.x)
            if (ew[2 * j + 1] != 0) atomicAnd(&s_ez, 0);
        for (int j = threadIdx.x; j < 24999; j += blockDim.x)
            if (bw[2 * j] > bw[2 * j + 1]) atomicOr(&s_bg, 1);
        __syncthreads();
        if (threadIdx.x == 0) { g_is64e = s_ez; g_is64b = s_bg; }
    }
}

// ------------------------- x -> fp16 mirror --------------------------------
__global__ void k_x2h(const float* __restrict__ x) {
    int i = blockIdx.x * blockDim.x + threadIdx.x;
    if (i < N_NODES * D / 4) {
        float4 v = *(const float4*)(x + (size_t)i * 4);
        uint2 pk;
        pk.x = pack_h2(v.x, v.y);
        pk.y = pack_h2(v.z, v.w);
        ((uint2*)g_hh)[i] = pk;
    }
}

// ------------------------- weight transpose (fp16) -------------------------
__global__ void k_wt(const float* __restrict__ w1, const float* __restrict__ w2) {
    int m = blockIdx.x;
    const float* W = (m < 4) ? (w1 + (size_t)m * D * D) : (w2 + (size_t)(m - 4) * D * D);
    for (int idx = threadIdx.x; idx < D * D; idx += blockDim.x) {
        int k = idx >> 7, n = idx & 127;
        g_wTh[m][n * D + k] = __float2half(W[idx]);   // B[n][k] = W[k][n]
    }
}

// ------------------------- CSR build ---------------------------------------
__global__ void k_hist(const void* __restrict__ e) {
    int i = blockIdx.x * blockDim.x + threadIdx.x;
    if (i < N_EDGES) atomicAdd(&g_cnt[e_at(e, (long long)N_EDGES + i)], 1);
}
__global__ void k_scan1() {
    __shared__ int sm[256];
    int t = threadIdx.x, idx = blockIdx.x * 256 + t;
    int v = (idx < N_NODES) ? g_cnt[idx] : 0;
    sm[t] = v; __syncthreads();
    for (int off = 1; off < 256; off <<= 1) {
        int u = (t >= off) ? sm[t - off] : 0;
        __syncthreads(); sm[t] += u; __syncthreads();
    }
    if (idx < N_NODES) g_cnt[idx] = sm[t] - v;
    if (t == 255) g_bsum[blockIdx.x] = sm[255];
}
__global__ void k_scan2() {
    __shared__ int sm[256];
    int t = threadIdx.x;
    int v = (t < NB_SCAN) ? g_bsum[t] : 0;
    sm[t] = v; __syncthreads();
    for (int off = 1; off < 256; off <<= 1) {
        int u = (t >= off) ? sm[t - off] : 0;
        __syncthreads(); sm[t] += u; __syncthreads();
    }
    if (t < NB_SCAN) g_boff[t] = sm[t] - v;
    if (t == NB_SCAN - 1) g_rowptr[N_NODES] = sm[t];
}
__global__ void k_scan3() {
    int idx = blockIdx.x * 256 + threadIdx.x;
    if (idx < N_NODES) {
        int rp = g_boff[blockIdx.x] + g_cnt[idx];
        g_rowptr[idx] = rp; g_cursor[idx] = rp;
    }
}
__global__ void k_fill(const void* __restrict__ e) {
    int i = blockIdx.x * blockDim.x + threadIdx.x;
    if (i < N_EDGES) {
        int s = e_at(e, i);
        int d = e_at(e, (long long)N_EDGES + i);
        g_col[atomicAdd(&g_cursor[d], 1)] = s;
    }
}

// ------------------------- graph ranges via binary search ------------------
__global__ void k_graphs(const void* __restrict__ batch) {
    int g = threadIdx.x;
    int lo = 0, hi = N_NODES;
    while (lo < hi) {
        int mid = (lo + hi) >> 1;
        if (b_at(batch, mid) < g) lo = mid + 1; else hi = mid;
    }
    g_gptr[g] = lo;
    if (g == 0) g_gptr[N_GRAPHS] = N_NODES;
    __syncthreads();
    int nxt = (g < N_GRAPHS - 1) ? g_gptr[g + 1] : N_NODES;
    g_gcnt[g] = fmaxf((float)(nxt - lo), 1.0f);
}

// ------------------------- aggregation (fp16 in, fp16 out) -----------------
__global__ void __launch_bounds__(256) k_agg() {
    int warp = (blockIdx.x * blockDim.x + threadIdx.x) >> 5;
    int lane = threadIdx.x & 31;
    if (warp >= N_NODES) return;
    int s = g_rowptr[warp], e = g_rowptr[warp + 1];
    float4 acc = make_float4(0.f, 0.f, 0.f, 0.f);
    acc_h4(acc, __ldg(((const uint2*)(g_hh + (size_t)warp * D)) + lane));
    int i = s;
    for (; i + 4 <= e; i += 4) {
        int s0 = g_col[i], s1 = g_col[i + 1], s2 = g_col[i + 2], s3 = g_col[i + 3];
        uint2 r0 = __ldg(((const uint2*)(g_hh + (size_t)s0 * D)) + lane);
        uint2 r1 = __ldg(((const uint2*)(g_hh + (size_t)s1 * D)) + lane);
        uint2 r2 = __ldg(((const uint2*)(g_hh + (size_t)s2 * D)) + lane);
        uint2 r3 = __ldg(((const uint2*)(g_hh + (size_t)s3 * D)) + lane);
        acc_h4(acc, r0); acc_h4(acc, r1); acc_h4(acc, r2); acc_h4(acc, r3);
    }
    for (; i < e; i++)
        acc_h4(acc, __ldg(((const uint2*)(g_hh + (size_t)g_col[i] * D)) + lane));
    uint2 pk;
    pk.x = pack_h2(acc.x, acc.y);
    pk.y = pack_h2(acc.z, acc.w);
    ((uint2*)(g_ah + (size_t)warp * D))[lane] = pk;
}

// ---- fused GIN MLP, fp16 mma m16n8k16, 64-row tile, ~52KB smem (occ 4) ---
#define SMEM_GIN ((64 * PADH + 128 * PADH) * 2)

__global__ void __launch_bounds__(256) k_gin(int layer,
                                             const float* __restrict__ bias1,
                                             const float* __restrict__ bias2,
                                             const void* __restrict__ batch,
                                             float* __restrict__ Hout) {
    extern __shared__ __half smh[];
    __half* As = smh;                   // [64][PADH]  A / H1 tile (fp16)
    __half* Bs = smh + 64 * PADH;       // [128][PADH] W tile; later Hs (float)
    uint32_t* As32 = (uint32_t*)As;
    uint32_t* Bs32 = (uint32_t*)Bs;
    __shared__ float b1s[128], b2s[128];
    __shared__ int gids[64];

    int tid = threadIdx.x, wid = tid >> 5, lane = tid & 31;
    int warp_m = wid & 1, warp_n = wid >> 1;     // 2 x 4 warp grid, 32x32 tiles
    int gID = lane >> 2, tig = lane & 3;
    int rb = blockIdx.x * 64;
    int nvalid = min(64, N_NODES - rb);

    // stage A (fp16): 64 rows x 16 uint4 = 1024, 4 iters
#pragma unroll
    for (int it = 0; it < 4; it++) {
        int idx = tid + it * 256;
        int r = idx >> 4, c8 = (idx & 15) * 8;   // 8 halfs per uint4
        uint4 v = make_uint4(0, 0, 0, 0);
        if (r < nvalid)
            v = *(const uint4*)(g_ah + (size_t)(rb + r) * D + c8);
        *(uint4*)(As + r * PADH + c8) = v;
    }
    // stage W1^T: 128 rows x 16 uint4 = 2048, 8 iters
#pragma unroll
    for (int it = 0; it < 8; it++) {
        int idx = tid + it * 256;
        int r = idx >> 4, c8 = (idx & 15) * 8;
        *(uint4*)(Bs + r * PADH + c8) = *(const uint4*)(g_wTh[layer] + r * D + c8);
    }
    if (tid < 128) b1s[tid] = bias1[tid];
    else b2s[tid - 128] = bias2[tid - 128];
    if (tid < 64) gids[tid] = (tid < nvalid) ? b_at(batch, rb + tid) : 0;
    __syncthreads();

    float c[2][4][4];

    // ---------------- GEMM1: H1 = relu(A @ W1 + b1) ----------------
#pragma unroll
    for (int i = 0; i < 2; i++)
#pragma unroll
        for (int j = 0; j < 4; j++)
#pragma unroll
            for (int q = 0; q < 4; q++) c[i][j][q] = 0.f;

#pragma unroll
    for (int kk = 0; kk < 8; kk++) {
        int kw = kk * 8 + tig;              // word offset within row
        uint32_t a[2][4];
#pragma unroll
        for (int i = 0; i < 2; i++) {
            int r0 = (warp_m * 32 + i * 16 + gID) * 68;
            a[i][0] = As32[r0 + kw];
            a[i][1] = As32[r0 + 8 * 68 + kw];
            a[i][2] = As32[r0 + kw + 4];
            a[i][3] = As32[r0 + 8 * 68 + kw + 4];
        }
#pragma unroll
        for (int j = 0; j < 4; j++) {
            int n = warp_n * 32 + j * 8 + gID;
            uint32_t b0 = Bs32[n * 68 + kw];
            uint32_t b1 = Bs32[n * 68 + kw + 4];
            mma_f16(c[0][j], a[0][0], a[0][1], a[0][2], a[0][3], b0, b1);
            mma_f16(c[1][j], a[1][0], a[1][1], a[1][2], a[1][3], b0, b1);
        }
    }
    __syncthreads();

    // H1 (fp16) -> As, stage W2^T -> Bs
#pragma unroll
    for (int i = 0; i < 2; i++) {
        int r0 = warp_m * 32 + i * 16 + gID;
#pragma unroll
        for (int j = 0; j < 4; j++) {
            int cb = warp_n * 32 + j * 8 + 2 * tig;        // col pair
            int w = warp_n * 16 + j * 4 + tig;             // word in row
            As32[r0 * 68 + w] =
                pack_h2(fmaxf(c[i][j][0] + b1s[cb], 0.f),
                        fmaxf(c[i][j][1] + b1s[cb + 1], 0.f));
            As32[(r0 + 8) * 68 + w] =
                pack_h2(fmaxf(c[i][j][2] + b1s[cb], 0.f),
                        fmaxf(c[i][j][3] + b1s[cb + 1], 0.f));
        }
    }
#pragma unroll
    for (int it = 0; it < 8; it++) {
        int idx = tid + it * 256;
        int r = idx >> 4, c8 = (idx & 15) * 8;
        *(uint4*)(Bs + r * PADH + c8) = *(const uint4*)(g_wTh[4 + layer] + r * D + c8);
    }
    __syncthreads();

    // ---------------- GEMM2: H = relu(H1 @ W2 + b2) ----------------
#pragma unroll
    for (int i = 0; i < 2; i++)
#pragma unroll
        for (int j = 0; j < 4; j++)
#pragma unroll
            for (int q = 0; q < 4; q++) c[i][j][q] = 0.f;

#pragma unroll
    for (int kk = 0; kk < 8; kk++) {
        int kw = kk * 8 + tig;
        uint32_t a[2][4];
#pragma unroll
        for (int i = 0; i < 2; i++) {
            int r0 = (warp_m * 32 + i * 16 + gID) * 68;
            a[i][0] = As32[r0 + kw];
            a[i][1] = As32[r0 + 8 * 68 + kw];
            a[i][2] = As32[r0 + kw + 4];
            a[i][3] = As32[r0 + 8 * 68 + kw + 4];
        }
#pragma unroll
        for (int j = 0; j < 4; j++) {
            int n = warp_n * 32 + j * 8 + gID;
            uint32_t b0 = Bs32[n * 68 + kw];
            uint32_t b1 = Bs32[n * 68 + kw + 4];
            mma_f16(c[0][j], a[0][0], a[0][1], a[0][2], a[0][3], b0, b1);
            mma_f16(c[1][j], a[1][0], a[1][1], a[1][2], a[1][3], b0, b1);
        }
    }
    __syncthreads();   // Bs reads done; reuse as float staging

    // epilogue: H -> global (fp32) + smem staging for stats
    float* Hs = (float*)Bs;
#pragma unroll
    for (int i = 0; i < 2; i++) {
        int lr0 = warp_m * 32 + i * 16 + gID;
        int lr1 = lr0 + 8;
#pragma unroll
        for (int j = 0; j < 4; j++) {
            int cb = warp_n * 32 + j * 8 + 2 * tig;
            float2 o0, o1;
            o0.x = fmaxf(c[i][j][0] + b2s[cb], 0.f);
            o0.y = fmaxf(c[i][j][1] + b2s[cb + 1], 0.f);
            o1.x = fmaxf(c[i][j][2] + b2s[cb], 0.f);
            o1.y = fmaxf(c[i][j][3] + b2s[cb + 1], 0.f);
            Hs[lr0 * PAD + cb] = o0.x;  Hs[lr0 * PAD + cb + 1] = o0.y;
            Hs[lr1 * PAD + cb] = o1.x;  Hs[lr1 * PAD + cb + 1] = o1.y;
            if (lr0 < nvalid) *(float2*)(Hout + (size_t)(rb + lr0) * D + cb) = o0;
            if (lr1 < nvalid) *(float2*)(Hout + (size_t)(rb + lr1) * D + cb) = o1;
        }
    }
    __syncthreads();

    // per-graph stats (sum, sumsq) from smem, 2 strips of 32 rows
    {
        int d = tid & 127, half = tid >> 7;
        int r0 = half * 32, r1 = min(r0 + 32, nvalid);
        if (r0 < nvalid) {
            int curg = gids[r0];
            float s = 0.f, q = 0.f;
            for (int r = r0; r < r1; r++) {
                int g = gids[r];
                if (g != curg) {
                    atomicAdd(&g_stat[layer][curg][0][d], s);
                    atomicAdd(&g_stat[layer][curg][1][d], q);
                    s = 0.f; q = 0.f; curg = g;
                }
                float v = Hs[r * PAD + d];
                s += v; q += v * v;
            }
            atomicAdd(&g_stat[layer][curg][0][d], s);
            atomicAdd(&g_stat[layer][curg][1][d], q);
        }
    }
}

// ------------------------- GraphNorm apply + relu --------------------------
__global__ void __launch_bounds__(256) k_gnapply(const void* __restrict__ batch,
                                                 const float* __restrict__ w,
                                                 const float* __restrict__ b,
                                                 const float* __restrict__ ms,
                                                 int layer, int last) {
    int warp = (blockIdx.x * blockDim.x + threadIdx.x) >> 5;
    int lane = threadIdx.x & 31;
    if (warp >= N_NODES) return;
    int g = b_at(batch, warp);
    float c = g_gcnt[g];
    int d0 = lane * 4;
    float4 h  = ((const float4*)(g_h + (size_t)warp * D))[lane];
    float4 s4 = *(const float4*)&g_stat[layer][g][0][d0];
    float4 q4 = *(const float4*)&g_stat[layer][g][1][d0];
    float4 ms4 = *(const float4*)(ms + layer * D + d0);
    float4 w4  = *(const float4*)(w  + layer * D + d0);
    float4 b4  = *(const float4*)(b  + layer * D + d0);
    float4 o;
#define GN1(X) {                                                   \
    float mean = s4.X / c;                                         \
    float aa = mean * ms4.X;                                       \
    float var = q4.X / c - 2.f * aa * mean + aa * aa;              \
    float rstd = rsqrtf(var + GN_EPS);                             \
    o.X = fmaxf(w4.X * (h.X - aa) * rstd + b4.X, 0.f); }
    GN1(x) GN1(y) GN1(z) GN1(w)
#undef GN1
    if (last) {
        atomicAdd(&g_pool[g * D + d0 + 0], o.x);
        atomicAdd(&g_pool[g * D + d0 + 1], o.y);
        atomicAdd(&g_pool[g * D + d0 + 2], o.z);
        atomicAdd(&g_pool[g * D + d0 + 3], o.w);
    } else {
        uint2 pk;
        pk.x = pack_h2(o.x, o.y);
        pk.y = pack_h2(o.z, o.w);
        ((uint2*)(g_hh + (size_t)warp * D))[lane] = pk;
    }
}

// ------------------------- final MLP + log_softmax -------------------------
__global__ void __launch_bounds__(128) k_mlp(const float* __restrict__ fw1,
                                             const float* __restrict__ fb1,
                                             const float* __restrict__ fw2,
                                             const float* __restrict__ fb2,
                                             const float* __restrict__ fw3,
                                             const float* __restrict__ fb3,
                                             float* __restrict__ out) {
    int g = blockIdx.x, t = threadIdx.x;
    __shared__ float v[D], v2[D], o[C], red[2];
    v[t] = g_pool[g * D + t];
    __syncthreads();
    float acc = fb1[t];
    for (int k = 0; k < D; k++) acc += v[k] * fw1[k * D + t];
    v2[t] = fmaxf(acc, 0.f);
    __syncthreads();
    acc = fb2[t];
    for (int k = 0; k < D; k++) acc += v2[k] * fw2[k * D + t];
    __syncthreads();
    v[t] = fmaxf(acc, 0.f);
    __syncthreads();
    if (t < C) {
        float a = fb3[t];
        for (int k = 0; k < D; k++) a += v[k] * fw3[k * C + t];
        o[t] = a;
    }
    __syncthreads();
    if (t == 0) {
        float m = -1e30f;
        for (int cc = 0; cc < C; cc++) m = fmaxf(m, o[cc]);
        float se = 0.f;
        for (int cc = 0; cc < C; cc++) se += expf(o[cc] - m);
        red[0] = m; red[1] = logf(se);
    }
    __syncthreads();
    if (t < C) out[g * C + t] = o[t] - red[0] - red[1];
}

// ------------------------- launcher ----------------------------------------
extern "C" void kernel_launch(void* const* d_in, const int* in_sizes, int n_in,
                              void* d_out, int out_size) {
    const float* x    = (const float*)d_in[0];
    const float* w1   = (const float*)d_in[1];
    const float* b1   = (const float*)d_in[2];
    const float* w2   = (const float*)d_in[3];
    const float* b2   = (const float*)d_in[4];
    const float* gnw  = (const float*)d_in[5];
    const float* gnb  = (const float*)d_in[6];
    const float* gns  = (const float*)d_in[7];
    const float* fw1  = (const float*)d_in[8];
    const float* fb1  = (const float*)d_in[9];
    const float* fw2  = (const float*)d_in[10];
    const float* fb2  = (const float*)d_in[11];
    const float* fw3  = (const float*)d_in[12];
    const float* fb3  = (const float*)d_in[13];
    const void*  edge  = d_in[14];
    const void*  batch = d_in[15];
    float* out = (float*)d_out;

    float* p_h;
    cudaGetSymbolAddress((void**)&p_h, g_h);
    cudaFuncSetAttribute(k_gin, cudaFuncAttributeMaxDynamicSharedMemorySize,
                         SMEM_GIN);

    // prologue
    k_prep<<<(ZERO_ELEMS + 255) / 256, 256>>>((const int*)edge, (const int*)batch);
    k_wt<<<8, 256>>>(w1, w2);
    k_x2h<<<(N_NODES * D / 4 + 255) / 256, 256>>>(x);
    k_hist<<<(N_EDGES + 255) / 256, 256>>>(edge);
    k_scan1<<<NB_SCAN, 256>>>();
    k_scan2<<<1, 256>>>();
    k_scan3<<<NB_SCAN, 256>>>();
    k_fill<<<(N_EDGES + 255) / 256, 256>>>(edge);
    k_graphs<<<1, N_GRAPHS>>>(batch);

    const int ginGrid = (N_NODES + 63) / 64;          // 782
    const int aggGrid = (N_NODES * 32 + 255) / 256;   // 6250

    for (int l = 0; l < L; l++) {
        k_agg<<<aggGrid, 256>>>();                        // read hh, write ah
        k_gin<<<ginGrid, 256, SMEM_GIN>>>(l,              // read ah, write h
                                          b1 + (size_t)l * D, b2 + (size_t)l * D,
                                          batch, p_h);
        k_gnapply<<<aggGrid, 256>>>(batch, gnw, gnb, gns, l, l == L - 1);
    }
    k_mlp<<<N_GRAPHS, 128>>>(fw1, fb1, fw2, fb2, fw3, fb3, out);
}

// round 11
// speedup vs baseline: 1.6808x; 1.0607x over previous
#include <cuda_runtime.h>
#include <cuda_fp16.h>
#include <cstdint>

#define N_NODES 50000
#define N_EDGES 800000
#define N_GRAPHS 128
#define D 128
#define L 4
#define C 10
#define GN_EPS 1e-5f
#define NB_SCAN 196
#define PAD 132          // float padding (stats staging)
#define PADH 136         // half padding (GEMM tiles), 68 words/row
#define ZERO_ELEMS (L * N_GRAPHS * 2 * D)

// ------------------------- device scratch (static, no allocs) -------------
__device__ __half g_h16[(size_t)N_NODES * D]; // un-normalized H (gin out, fp16)
__device__ __half g_ah[(size_t)N_NODES * D];  // agg output (fp16, gin input)
__device__ __half g_hh[(size_t)N_NODES * D];  // fp16 normalized state
__device__ int    g_rowptr[N_NODES + 1];
__device__ int    g_cursor[N_NODES];
__device__ int    g_cnt[N_NODES];
__device__ int    g_col[N_EDGES];
__device__ int    g_bsum[NB_SCAN];
__device__ int    g_boff[NB_SCAN];
__device__ int    g_gptr[N_GRAPHS + 1];
__device__ float  g_gcnt[N_GRAPHS];
__device__ float  g_pool[N_GRAPHS * D];
__device__ float  g_stat[L][N_GRAPHS][2][D];
__device__ __half g_wTh[8][16384];            // W^T fp16, B[n][k]
__device__ int    g_is64e;
__device__ int    g_is64b;

// ------------------------- helpers ----------------------------------------
__device__ __forceinline__ int e_at(const void* p, long long i) {
    if (g_is64e) return (int)((const long long*)p)[i];
    return ((const int*)p)[i];
}
__device__ __forceinline__ int b_at(const void* p, long long i) {
    if (g_is64b) return (int)((const long long*)p)[i];
    return ((const int*)p)[i];
}

// mma.sync m16n8k16 fp16 (fp32 accum): C += A*B
__device__ __forceinline__ void mma_f16(float c[4], uint32_t a0, uint32_t a1,
                                        uint32_t a2, uint32_t a3,
                                        uint32_t b0, uint32_t b1) {
    asm volatile(
        "mma.sync.aligned.m16n8k16.row.col.f32.f16.f16.f32 "
        "{%0,%1,%2,%3}, {%4,%5,%6,%7}, {%8,%9}, {%0,%1,%2,%3};"
        : "+f"(c[0]), "+f"(c[1]), "+f"(c[2]), "+f"(c[3])
        : "r"(a0), "r"(a1), "r"(a2), "r"(a3), "r"(b0), "r"(b1));
}

__device__ __forceinline__ void acc_h4(float4& acc, uint2 r) {
    float2 f0 = __half22float2(*reinterpret_cast<__half2*>(&r.x));
    float2 f1 = __half22float2(*reinterpret_cast<__half2*>(&r.y));
    acc.x += f0.x; acc.y += f0.y; acc.z += f1.x; acc.w += f1.y;
}
__device__ __forceinline__ uint32_t pack_h2(float x, float y) {
    __half2 h = __floats2half2_rn(x, y);
    return *reinterpret_cast<uint32_t*>(&h);
}

// --------- fused prologue: zero + detect + graphs + wT + x mirror ----------
// Block 0 serializes dtype detection then graph binary search (the only
// ordering dependency). All blocks grid-stride the bulk work.
__global__ void k_prep(const int* __restrict__ ew, const int* __restrict__ bw,
                       const float* __restrict__ w1, const float* __restrict__ w2,
                       const float* __restrict__ x) {
    int gsz = gridDim.x * blockDim.x;
    int gid0 = blockIdx.x * blockDim.x + threadIdx.x;

    if (blockIdx.x == 0) {
        __shared__ int s_ez, s_bg;
        if (threadIdx.x == 0) { s_ez = 1; s_bg = 0; }
        __syncthreads();
        for (int j = threadIdx.x; j < 128; j += blockDim.x)
            if (ew[2 * j + 1] != 0) atomicAnd(&s_ez, 0);
        for (int j = threadIdx.x; j < 24999; j += blockDim.x)
            if (bw[2 * j] > bw[2 * j + 1]) atomicOr(&s_bg, 1);
        __syncthreads();
        if (threadIdx.x == 0) { g_is64e = s_ez; g_is64b = s_bg; }
        // graph ranges (needs s_bg, available in shared)
        if (threadIdx.x < N_GRAPHS) {
            int g = threadIdx.x;
            int lo = 0, hi = N_NODES;
            while (lo < hi) {
                int mid = (lo + hi) >> 1;
                int v = s_bg ? (int)((const long long*)bw)[mid] : bw[mid];
                if (v < g) lo = mid + 1; else hi = mid;
            }
            g_gptr[g] = lo;
            if (g == 0) g_gptr[N_GRAPHS] = N_NODES;
        }
        __syncthreads();
        if (threadIdx.x < N_GRAPHS) {
            int g = threadIdx.x;
            int nxt = (g < N_GRAPHS - 1) ? g_gptr[g + 1] : N_NODES;
            g_gcnt[g] = fmaxf((float)(nxt - g_gptr[g]), 1.0f);
        }
    }

    // zero scratch
    for (int i = gid0; i < ZERO_ELEMS; i += gsz) {
        if (i < N_NODES) g_cnt[i] = 0;
        (&g_stat[0][0][0][0])[i] = 0.f;
        if (i < N_GRAPHS * D) g_pool[i] = 0.f;
    }
    // weight transpose fp16: 8 matrices x 16384
    for (int i = gid0; i < 8 * 16384; i += gsz) {
        int m = i >> 14, idx = i & 16383;
        int k = idx >> 7, n = idx & 127;
        const float* W = (m < 4) ? (w1 + (size_t)m * D * D)
                                 : (w2 + (size_t)(m - 4) * D * D);
        g_wTh[m][n * D + k] = __float2half(W[idx]);
    }
    // x -> fp16 mirror: N*D/4 uint2
    for (int i = gid0; i < N_NODES * D / 4; i += gsz) {
        float4 v = *(const float4*)(x + (size_t)i * 4);
        uint2 pk;
        pk.x = pack_h2(v.x, v.y);
        pk.y = pack_h2(v.z, v.w);
        ((uint2*)g_hh)[i] = pk;
    }
}

// ------------------------- CSR build ---------------------------------------
__global__ void k_hist(const void* __restrict__ e) {
    int i = blockIdx.x * blockDim.x + threadIdx.x;
    if (i < N_EDGES) atomicAdd(&g_cnt[e_at(e, (long long)N_EDGES + i)], 1);
}
__global__ void k_scan1() {
    __shared__ int sm[256];
    int t = threadIdx.x, idx = blockIdx.x * 256 + t;
    int v = (idx < N_NODES) ? g_cnt[idx] : 0;
    sm[t] = v; __syncthreads();
    for (int off = 1; off < 256; off <<= 1) {
        int u = (t >= off) ? sm[t - off] : 0;
        __syncthreads(); sm[t] += u; __syncthreads();
    }
    if (idx < N_NODES) g_cnt[idx] = sm[t] - v;
    if (t == 255) g_bsum[blockIdx.x] = sm[255];
}
__global__ void k_scan2() {
    __shared__ int sm[256];
    int t = threadIdx.x;
    int v = (t < NB_SCAN) ? g_bsum[t] : 0;
    sm[t] = v; __syncthreads();
    for (int off = 1; off < 256; off <<= 1) {
        int u = (t >= off) ? sm[t - off] : 0;
        __syncthreads(); sm[t] += u; __syncthreads();
    }
    if (t < NB_SCAN) g_boff[t] = sm[t] - v;
    if (t == NB_SCAN - 1) g_rowptr[N_NODES] = sm[t];
}
__global__ void k_scan3() {
    int idx = blockIdx.x * 256 + threadIdx.x;
    if (idx < N_NODES) {
        int rp = g_boff[blockIdx.x] + g_cnt[idx];
        g_rowptr[idx] = rp; g_cursor[idx] = rp;
    }
}
__global__ void k_fill(const void* __restrict__ e) {
    int i = blockIdx.x * blockDim.x + threadIdx.x;
    if (i < N_EDGES) {
        int s = e_at(e, i);
        int d = e_at(e, (long long)N_EDGES + i);
        g_col[atomicAdd(&g_cursor[d], 1)] = s;
    }
}

// ------------------------- aggregation (fp16 in, fp16 out) -----------------
__global__ void __launch_bounds__(256) k_agg() {
    int warp = (blockIdx.x * blockDim.x + threadIdx.x) >> 5;
    int lane = threadIdx.x & 31;
    if (warp >= N_NODES) return;
    int s = g_rowptr[warp], e = g_rowptr[warp + 1];
    float4 acc = make_float4(0.f, 0.f, 0.f, 0.f);
    acc_h4(acc, __ldg(((const uint2*)(g_hh + (size_t)warp * D)) + lane));
    int i = s;
    for (; i + 4 <= e; i += 4) {
        int s0 = g_col[i], s1 = g_col[i + 1], s2 = g_col[i + 2], s3 = g_col[i + 3];
        uint2 r0 = __ldg(((const uint2*)(g_hh + (size_t)s0 * D)) + lane);
        uint2 r1 = __ldg(((const uint2*)(g_hh + (size_t)s1 * D)) + lane);
        uint2 r2 = __ldg(((const uint2*)(g_hh + (size_t)s2 * D)) + lane);
        uint2 r3 = __ldg(((const uint2*)(g_hh + (size_t)s3 * D)) + lane);
        acc_h4(acc, r0); acc_h4(acc, r1); acc_h4(acc, r2); acc_h4(acc, r3);
    }
    for (; i < e; i++)
        acc_h4(acc, __ldg(((const uint2*)(g_hh + (size_t)g_col[i] * D)) + lane));
    uint2 pk;
    pk.x = pack_h2(acc.x, acc.y);
    pk.y = pack_h2(acc.z, acc.w);
    ((uint2*)(g_ah + (size_t)warp * D))[lane] = pk;
}

// ---- fused GIN MLP, fp16 mma m16n8k16, 128-row tile, 69.6KB smem (occ 3) --
#define SMEM_GIN ((128 * PADH + 128 * PADH) * 2)

__global__ void __launch_bounds__(256) k_gin(int layer,
                                             const float* __restrict__ bias1,
                                             const float* __restrict__ bias2,
                                             const void* __restrict__ batch) {
    extern __shared__ __half smh[];
    __half* As = smh;                    // [128][PADH]  A / H1 tile
    __half* Bs = smh + 128 * PADH;       // [128][PADH]  W tile
    uint32_t* As32 = (uint32_t*)As;
    uint32_t* Bs32 = (uint32_t*)Bs;
    __shared__ float b1s[128], b2s[128];
    __shared__ int gids[128];

    int tid = threadIdx.x, wid = tid >> 5, lane = tid & 31;
    int warp_m = wid & 3, warp_n = wid >> 2;     // 4 x 2 warp grid, 32x64 tiles
    int gID = lane >> 2, tig = lane & 3;
    int rb = blockIdx.x * 128;
    int nvalid = min(128, N_NODES - rb);

    // stage A (fp16): 128 rows x 16 uint4 = 2048, 8 iters
#pragma unroll
    for (int it = 0; it < 8; it++) {
        int idx = tid + it * 256;
        int r = idx >> 4, c8 = (idx & 15) * 8;
        uint4 v = make_uint4(0, 0, 0, 0);
        if (r < nvalid)
            v = *(const uint4*)(g_ah + (size_t)(rb + r) * D + c8);
        *(uint4*)(As + r * PADH + c8) = v;
    }
    // stage W1^T
#pragma unroll
    for (int it = 0; it < 8; it++) {
        int idx = tid + it * 256;
        int r = idx >> 4, c8 = (idx & 15) * 8;
        *(uint4*)(Bs + r * PADH + c8) = *(const uint4*)(g_wTh[layer] + r * D + c8);
    }
    if (tid < 128) b1s[tid] = bias1[tid];
    else b2s[tid - 128] = bias2[tid - 128];
    if (tid < 128) gids[tid] = (tid < nvalid) ? b_at(batch, rb + tid) : 0;
    __syncthreads();

    float c[2][8][4];

    // ---------------- GEMM1: H1 = relu(A @ W1 + b1) ----------------
#pragma unroll
    for (int i = 0; i < 2; i++)
#pragma unroll
        for (int j = 0; j < 8; j++)
#pragma unroll
            for (int q = 0; q < 4; q++) c[i][j][q] = 0.f;

#pragma unroll
    for (int kk = 0; kk < 8; kk++) {
        int kw = kk * 8 + tig;
        uint32_t a[2][4];
#pragma unroll
        for (int i = 0; i < 2; i++) {
            int r0 = (warp_m * 32 + i * 16 + gID) * 68;
            a[i][0] = As32[r0 + kw];
            a[i][1] = As32[r0 + 8 * 68 + kw];
            a[i][2] = As32[r0 + kw + 4];
            a[i][3] = As32[r0 + 8 * 68 + kw + 4];
        }
#pragma unroll
        for (int j = 0; j < 8; j++) {
            int n = warp_n * 64 + j * 8 + gID;
            uint32_t b0 = Bs32[n * 68 + kw];
            uint32_t b1 = Bs32[n * 68 + kw + 4];
            mma_f16(c[0][j], a[0][0], a[0][1], a[0][2], a[0][3], b0, b1);
            mma_f16(c[1][j], a[1][0], a[1][1], a[1][2], a[1][3], b0, b1);
        }
    }
    __syncthreads();

    // H1 (fp16) -> As, stage W2^T -> Bs
#pragma unroll
    for (int i = 0; i < 2; i++) {
        int r0 = warp_m * 32 + i * 16 + gID;
#pragma unroll
        for (int j = 0; j < 8; j++) {
            int cb = warp_n * 64 + j * 8 + 2 * tig;
            int w = warp_n * 32 + j * 4 + tig;
            As32[r0 * 68 + w] =
                pack_h2(fmaxf(c[i][j][0] + b1s[cb], 0.f),
                        fmaxf(c[i][j][1] + b1s[cb + 1], 0.f));
            As32[(r0 + 8) * 68 + w] =
                pack_h2(fmaxf(c[i][j][2] + b1s[cb], 0.f),
                        fmaxf(c[i][j][3] + b1s[cb + 1], 0.f));
        }
    }
#pragma unroll
    for (int it = 0; it < 8; it++) {
        int idx = tid + it * 256;
        int r = idx >> 4, c8 = (idx & 15) * 8;
        *(uint4*)(Bs + r * PADH + c8) = *(const uint4*)(g_wTh[4 + layer] + r * D + c8);
    }
    __syncthreads();

    // ---------------- GEMM2: H = relu(H1 @ W2 + b2) ----------------
#pragma unroll
    for (int i = 0; i < 2; i++)
#pragma unroll
        for (int j = 0; j < 8; j++)
#pragma unroll
            for (int q = 0; q < 4; q++) c[i][j][q] = 0.f;

#pragma unroll
    for (int kk = 0; kk < 8; kk++) {
        int kw = kk * 8 + tig;
        uint32_t a[2][4];
#pragma unroll
        for (int i = 0; i < 2; i++) {
            int r0 = (warp_m * 32 + i * 16 + gID) * 68;
            a[i][0] = As32[r0 + kw];
            a[i][1] = As32[r0 + 8 * 68 + kw];
            a[i][2] = As32[r0 + kw + 4];
            a[i][3] = As32[r0 + 8 * 68 + kw + 4];
        }
#pragma unroll
        for (int j = 0; j < 8; j++) {
            int n = warp_n * 64 + j * 8 + gID;
            uint32_t b0 = Bs32[n * 68 + kw];
            uint32_t b1 = Bs32[n * 68 + kw + 4];
            mma_f16(c[0][j], a[0][0], a[0][1], a[0][2], a[0][3], b0, b1);
            mma_f16(c[1][j], a[1][0], a[1][1], a[1][2], a[1][3], b0, b1);
        }
    }
    __syncthreads();   // As & Bs reads done; reuse ALL smem as float staging

    // epilogue: H -> global (fp16) + smem staging for stats (fp32)
    float* Hs = (float*)smh;             // [128][PAD] floats = 67.6KB <= 69.6KB
#pragma unroll
    for (int i = 0; i < 2; i++) {
        int lr0 = warp_m * 32 + i * 16 + gID;
        int lr1 = lr0 + 8;
#pragma unroll
        for (int j = 0; j < 8; j++) {
            int cb = warp_n * 64 + j * 8 + 2 * tig;
            float o00 = fmaxf(c[i][j][0] + b2s[cb], 0.f);
            float o01 = fmaxf(c[i][j][1] + b2s[cb + 1], 0.f);
            float o10 = fmaxf(c[i][j][2] + b2s[cb], 0.f);
            float o11 = fmaxf(c[i][j][3] + b2s[cb + 1], 0.f);
            Hs[lr0 * PAD + cb] = o00;  Hs[lr0 * PAD + cb + 1] = o01;
            Hs[lr1 * PAD + cb] = o10;  Hs[lr1 * PAD + cb + 1] = o11;
            if (lr0 < nvalid)
                *(uint32_t*)(g_h16 + (size_t)(rb + lr0) * D + cb) = pack_h2(o00, o01);
            if (lr1 < nvalid)
                *(uint32_t*)(g_h16 + (size_t)(rb + lr1) * D + cb) = pack_h2(o10, o11);
        }
    }
    __syncthreads();

    // per-graph stats (sum, sumsq): 2 strips of 64 rows
    {
        int d = tid & 127, half = tid >> 7;
        int r0 = half * 64, r1 = min(r0 + 64, nvalid);
        if (r0 < nvalid) {
            int curg = gids[r0];
            float s = 0.f, q = 0.f;
            for (int r = r0; r < r1; r++) {
                int g = gids[r];
                if (g != curg) {
                    atomicAdd(&g_stat[layer][curg][0][d], s);
                    atomicAdd(&g_stat[layer][curg][1][d], q);
                    s = 0.f; q = 0.f; curg = g;
                }
                float v = Hs[r * PAD + d];
                s += v; q += v * v;
            }
            atomicAdd(&g_stat[layer][curg][0][d], s);
            atomicAdd(&g_stat[layer][curg][1][d], q);
        }
    }
}

// ------------------------- GraphNorm apply + relu --------------------------
// Reads g_h16 (fp16 gin out), writes g_hh (fp16) or pool (fp32 atomics).
__global__ void __launch_bounds__(256) k_gnapply(const void* __restrict__ batch,
                                                 const float* __restrict__ w,
                                                 const float* __restrict__ b,
                                                 const float* __restrict__ ms,
                                                 int layer, int last) {
    int warp = (blockIdx.x * blockDim.x + threadIdx.x) >> 5;
    int lane = threadIdx.x & 31;
    if (warp >= N_NODES) return;
    int g = b_at(batch, warp);
    float c = g_gcnt[g];
    int d0 = lane * 4;
    uint2 hr = ((const uint2*)(g_h16 + (size_t)warp * D))[lane];
    float2 hf0 = __half22float2(*reinterpret_cast<__half2*>(&hr.x));
    float2 hf1 = __half22float2(*reinterpret_cast<__half2*>(&hr.y));
    float4 h = make_float4(hf0.x, hf0.y, hf1.x, hf1.y);
    float4 s4 = *(const float4*)&g_stat[layer][g][0][d0];
    float4 q4 = *(const float4*)&g_stat[layer][g][1][d0];
    float4 ms4 = *(const float4*)(ms + layer * D + d0);
    float4 w4  = *(const float4*)(w  + layer * D + d0);
    float4 b4  = *(const float4*)(b  + layer * D + d0);
    float4 o;
#define GN1(X) {                                                   \
    float mean = s4.X / c;                                         \
    float aa = mean * ms4.X;                                       \
    float var = q4.X / c - 2.f * aa * mean + aa * aa;              \
    float rstd = rsqrtf(var + GN_EPS);                             \
    o.X = fmaxf(w4.X * (h.X - aa) * rstd + b4.X, 0.f); }
    GN1(x) GN1(y) GN1(z) GN1(w)
#undef GN1
    if (last) {
        atomicAdd(&g_pool[g * D + d0 + 0], o.x);
        atomicAdd(&g_pool[g * D + d0 + 1], o.y);
        atomicAdd(&g_pool[g * D + d0 + 2], o.z);
        atomicAdd(&g_pool[g * D + d0 + 3], o.w);
    } else {
        uint2 pk;
        pk.x = pack_h2(o.x, o.y);
        pk.y = pack_h2(o.z, o.w);
        ((uint2*)(g_hh + (size_t)warp * D))[lane] = pk;
    }
}

// ------------------------- final MLP + log_softmax -------------------------
__global__ void __launch_bounds__(128) k_mlp(const float* __restrict__ fw1,
                                             const float* __restrict__ fb1,
                                             const float* __restrict__ fw2,
                                             const float* __restrict__ fb2,
                                             const float* __restrict__ fw3,
                                             const float* __restrict__ fb3,
                                             float* __restrict__ out) {
    int g = blockIdx.x, t = threadIdx.x;
    __shared__ float v[D], v2[D], o[C], red[2];
    v[t] = g_pool[g * D + t];
    __syncthreads();
    float acc = fb1[t];
    for (int k = 0; k < D; k++) acc += v[k] * fw1[k * D + t];
    v2[t] = fmaxf(acc, 0.f);
    __syncthreads();
    acc = fb2[t];
    for (int k = 0; k < D; k++) acc += v2[k] * fw2[k * D + t];
    __syncthreads();
    v[t] = fmaxf(acc, 0.f);
    __syncthreads();
    if (t < C) {
        float a = fb3[t];
        for (int k = 0; k < D; k++) a += v[k] * fw3[k * C + t];
        o[t] = a;
    }
    __syncthreads();
    if (t == 0) {
        float m = -1e30f;
        for (int cc = 0; cc < C; cc++) m = fmaxf(m, o[cc]);
        float se = 0.f;
        for (int cc = 0; cc < C; cc++) se += expf(o[cc] - m);
        red[0] = m; red[1] = logf(se);
    }
    __syncthreads();
    if (t < C) out[g * C + t] = o[t] - red[0] - red[1];
}

// ------------------------- launcher ----------------------------------------
extern "C" void kernel_launch(void* const* d_in, const int* in_sizes, int n_in,
                              void* d_out, int out_size) {
    const float* x    = (const float*)d_in[0];
    const float* w1   = (const float*)d_in[1];
    const float* b1   = (const float*)d_in[2];
    const float* w2   = (const float*)d_in[3];
    const float* b2   = (const float*)d_in[4];
    const float* gnw  = (const float*)d_in[5];
    const float* gnb  = (const float*)d_in[6];
    const float* gns  = (const float*)d_in[7];
    const float* fw1  = (const float*)d_in[8];
    const float* fb1  = (const float*)d_in[9];
    const float* fw2  = (const float*)d_in[10];
    const float* fb2  = (const float*)d_in[11];
    const float* fw3  = (const float*)d_in[12];
    const float* fb3  = (const float*)d_in[13];
    const void*  edge  = d_in[14];
    const void*  batch = d_in[15];
    float* out = (float*)d_out;

    cudaFuncSetAttribute(k_gin, cudaFuncAttributeMaxDynamicSharedMemorySize,
                         SMEM_GIN);

    // fused prologue (zero + detect + graphs + wT + x mirror), then CSR
    k_prep<<<1024, 256>>>((const int*)edge, (const int*)batch, w1, w2, x);
    k_hist<<<(N_EDGES + 255) / 256, 256>>>(edge);
    k_scan1<<<NB_SCAN, 256>>>();
    k_scan2<<<1, 256>>>();
    k_scan3<<<NB_SCAN, 256>>>();
    k_fill<<<(N_EDGES + 255) / 256, 256>>>(edge);

    const int ginGrid = (N_NODES + 127) / 128;        // 391
    const int aggGrid = (N_NODES * 32 + 255) / 256;   // 6250

    for (int l = 0; l < L; l++) {
        k_agg<<<aggGrid, 256>>>();                        // read hh, write ah
        k_gin<<<ginGrid, 256, SMEM_GIN>>>(l,              // read ah, write h16
                                          b1 + (size_t)l * D, b2 + (size_t)l * D,
                                          batch);
        k_gnapply<<<aggGrid, 256>>>(batch, gnw, gnb, gns, l, l == L - 1);
    }
    k_mlp<<<N_GRAPHS, 128>>>(fw1, fb1, fw2, fb2, fw3, fb3, out);
}

// round 12
// speedup vs baseline: 1.7024x; 1.0128x over previous
#include <cuda_runtime.h>
#include <cuda_fp16.h>
#include <cstdint>

#define N_NODES 50000
#define N_EDGES 800000
#define N_GRAPHS 128
#define D 128
#define L 4
#define C 10
#define GN_EPS 1e-5f
#define NB_SCAN 196
#define PAD 132          // float padding (stats staging)
#define PADH 136         // half padding (GEMM tiles), 68 words/row
#define ZERO_ELEMS (L * N_GRAPHS * 2 * D)

// ------------------------- device scratch (static, no allocs) -------------
__device__ __half g_h16[(size_t)N_NODES * D]; // un-normalized H (gin out, fp16)
__device__ __half g_ah[(size_t)N_NODES * D];  // agg output (fp16, gin input)
__device__ __half g_hh[(size_t)N_NODES * D];  // fp16 normalized state
__device__ int    g_rowptr[N_NODES + 1];
__device__ int    g_cursor[N_NODES];
__device__ int    g_cnt[N_NODES];
__device__ int    g_col[N_EDGES];
__device__ int    g_gptr[N_GRAPHS + 1];
__device__ float  g_gcnt[N_GRAPHS];
__device__ float  g_pool[N_GRAPHS * D];
__device__ float  g_stat[L][N_GRAPHS][2][D];
__device__ __half g_wTh[8][16384];            // W^T fp16, B[n][k]
__device__ int    g_is64e;
__device__ int    g_is64b;

// ------------------------- helpers ----------------------------------------
__device__ __forceinline__ int e_at(const void* p, long long i) {
    if (g_is64e) return (int)((const long long*)p)[i];
    return ((const int*)p)[i];
}
__device__ __forceinline__ int b_at(const void* p, long long i) {
    if (g_is64b) return (int)((const long long*)p)[i];
    return ((const int*)p)[i];
}

// mma.sync m16n8k16 fp16 (fp32 accum): C += A*B
__device__ __forceinline__ void mma_f16(float c[4], uint32_t a0, uint32_t a1,
                                        uint32_t a2, uint32_t a3,
                                        uint32_t b0, uint32_t b1) {
    asm volatile(
        "mma.sync.aligned.m16n8k16.row.col.f32.f16.f16.f32 "
        "{%0,%1,%2,%3}, {%4,%5,%6,%7}, {%8,%9}, {%0,%1,%2,%3};"
        : "+f"(c[0]), "+f"(c[1]), "+f"(c[2]), "+f"(c[3])
        : "r"(a0), "r"(a1), "r"(a2), "r"(a3), "r"(b0), "r"(b1));
}

__device__ __forceinline__ void acc_h4(float4& acc, uint2 r) {
    float2 f0 = __half22float2(*reinterpret_cast<__half2*>(&r.x));
    float2 f1 = __half22float2(*reinterpret_cast<__half2*>(&r.y));
    acc.x += f0.x; acc.y += f0.y; acc.z += f1.x; acc.w += f1.y;
}
__device__ __forceinline__ uint32_t pack_h2(float x, float y) {
    __half2 h = __floats2half2_rn(x, y);
    return *reinterpret_cast<uint32_t*>(&h);
}

// --------- fused prologue: zero + detect + graphs + wT + x mirror ----------
__global__ void k_prep(const int* __restrict__ ew, const int* __restrict__ bw,
                       const float* __restrict__ w1, const float* __restrict__ w2,
                       const float* __restrict__ x) {
    int gsz = gridDim.x * blockDim.x;
    int gid0 = blockIdx.x * blockDim.x + threadIdx.x;

    if (blockIdx.x == 0) {
        __shared__ int s_ez, s_bg;
        if (threadIdx.x == 0) { s_ez = 1; s_bg = 0; }
        __syncthreads();
        for (int j = threadIdx.x; j < 128; j += blockDim.x)
            if (ew[2 * j + 1] != 0) atomicAnd(&s_ez, 0);
        for (int j = threadIdx.x; j < 24999; j += blockDim.x)
            if (bw[2 * j] > bw[2 * j + 1]) atomicOr(&s_bg, 1);
        __syncthreads();
        if (threadIdx.x == 0) { g_is64e = s_ez; g_is64b = s_bg; }
        if (threadIdx.x < N_GRAPHS) {
            int g = threadIdx.x;
            int lo = 0, hi = N_NODES;
            while (lo < hi) {
                int mid = (lo + hi) >> 1;
                int v = s_bg ? (int)((const long long*)bw)[mid] : bw[mid];
                if (v < g) lo = mid + 1; else hi = mid;
            }
            g_gptr[g] = lo;
            if (g == 0) g_gptr[N_GRAPHS] = N_NODES;
        }
        __syncthreads();
        if (threadIdx.x < N_GRAPHS) {
            int g = threadIdx.x;
            int nxt = (g < N_GRAPHS - 1) ? g_gptr[g + 1] : N_NODES;
            g_gcnt[g] = fmaxf((float)(nxt - g_gptr[g]), 1.0f);
        }
    }

    for (int i = gid0; i < ZERO_ELEMS; i += gsz) {
        if (i < N_NODES) g_cnt[i] = 0;
        (&g_stat[0][0][0][0])[i] = 0.f;
        if (i < N_GRAPHS * D) g_pool[i] = 0.f;
    }
    for (int i = gid0; i < 8 * 16384; i += gsz) {
        int m = i >> 14, idx = i & 16383;
        int k = idx >> 7, n = idx & 127;
        const float* W = (m < 4) ? (w1 + (size_t)m * D * D)
                                 : (w2 + (size_t)(m - 4) * D * D);
        g_wTh[m][n * D + k] = __float2half(W[idx]);
    }
    for (int i = gid0; i < N_NODES * D / 4; i += gsz) {
        float4 v = *(const float4*)(x + (size_t)i * 4);
        uint2 pk;
        pk.x = pack_h2(v.x, v.y);
        pk.y = pack_h2(v.z, v.w);
        ((uint2*)g_hh)[i] = pk;
    }
}

// ------------------------- CSR build ---------------------------------------
__global__ void k_hist(const void* __restrict__ e) {
    int i = blockIdx.x * blockDim.x + threadIdx.x;
    if (i < N_EDGES) atomicAdd(&g_cnt[e_at(e, (long long)N_EDGES + i)], 1);
}

// single-kernel scan: block b brute-force sums counts[0, b*256) in parallel
// (no inter-block protocol), then local-scans its own 256 counts.
__global__ void k_scan() {
    __shared__ int red[256];
    int t = threadIdx.x, b = blockIdx.x;
    int idx = b * 256 + t;

    int base = 0;
    for (int i = t; i < b * 256; i += 256) base += g_cnt[i];
    red[t] = base;
    __syncthreads();
    for (int off = 128; off > 0; off >>= 1) {
        if (t < off) red[t] += red[t + off];
        __syncthreads();
    }
    int blockBase = red[0];
    __syncthreads();

    int v = (idx < N_NODES) ? g_cnt[idx] : 0;
    red[t] = v;
    __syncthreads();
    for (int off = 1; off < 256; off <<= 1) {
        int u = (t >= off) ? red[t - off] : 0;
        __syncthreads(); red[t] += u; __syncthreads();
    }
    if (idx < N_NODES) {
        int rp = blockBase + red[t] - v;
        g_rowptr[idx] = rp; g_cursor[idx] = rp;
    }
    if (b == NB_SCAN - 1 && t == 255) g_rowptr[N_NODES] = blockBase + red[255];
}

__global__ void k_fill(const void* __restrict__ e) {
    int i = blockIdx.x * blockDim.x + threadIdx.x;
    if (i < N_EDGES) {
        int s = e_at(e, i);
        int d = e_at(e, (long long)N_EDGES + i);
        g_col[atomicAdd(&g_cursor[d], 1)] = s;
    }
}

// ------------------------- aggregation (fp16 in, fp16 out) -----------------
__global__ void __launch_bounds__(256) k_agg() {
    int warp = (blockIdx.x * blockDim.x + threadIdx.x) >> 5;
    int lane = threadIdx.x & 31;
    if (warp >= N_NODES) return;
    int s = g_rowptr[warp], e = g_rowptr[warp + 1];
    float4 acc = make_float4(0.f, 0.f, 0.f, 0.f);
    acc_h4(acc, __ldg(((const uint2*)(g_hh + (size_t)warp * D)) + lane));
    int i = s;
    for (; i + 4 <= e; i += 4) {
        int s0 = g_col[i], s1 = g_col[i + 1], s2 = g_col[i + 2], s3 = g_col[i + 3];
        uint2 r0 = __ldg(((const uint2*)(g_hh + (size_t)s0 * D)) + lane);
        uint2 r1 = __ldg(((const uint2*)(g_hh + (size_t)s1 * D)) + lane);
        uint2 r2 = __ldg(((const uint2*)(g_hh + (size_t)s2 * D)) + lane);
        uint2 r3 = __ldg(((const uint2*)(g_hh + (size_t)s3 * D)) + lane);
        acc_h4(acc, r0); acc_h4(acc, r1); acc_h4(acc, r2); acc_h4(acc, r3);
    }
    for (; i < e; i++)
        acc_h4(acc, __ldg(((const uint2*)(g_hh + (size_t)g_col[i] * D)) + lane));
    uint2 pk;
    pk.x = pack_h2(acc.x, acc.y);
    pk.y = pack_h2(acc.z, acc.w);
    ((uint2*)(g_ah + (size_t)warp * D))[lane] = pk;
}

// ---- fused GIN MLP, fp16 mma, 128-row tile, 512 threads (16 warps) --------
#define SMEM_GIN ((128 * PADH + 128 * PADH) * 2)

__global__ void __launch_bounds__(512) k_gin(int layer,
                                             const float* __restrict__ bias1,
                                             const float* __restrict__ bias2,
                                             const void* __restrict__ batch) {
    extern __shared__ __half smh[];
    __half* As = smh;                    // [128][PADH]  A / H1 tile
    __half* Bs = smh + 128 * PADH;       // [128][PADH]  W tile
    uint32_t* As32 = (uint32_t*)As;
    uint32_t* Bs32 = (uint32_t*)Bs;
    __shared__ float b1s[128], b2s[128];
    __shared__ int gids[128];

    int tid = threadIdx.x, lane = tid & 31, wid = tid >> 5;
    int warp_m = wid & 3, warp_n = wid >> 2;     // 4 x 4 warp grid, 32x32 tiles
    int gID = lane >> 2, tig = lane & 3;
    int rb = blockIdx.x * 128;
    int nvalid = min(128, N_NODES - rb);

    // stage A (fp16): 2048 uint4, 4 iters @512thr
#pragma unroll
    for (int it = 0; it < 4; it++) {
        int idx = tid + it * 512;
        int r = idx >> 4, c8 = (idx & 15) * 8;
        uint4 v = make_uint4(0, 0, 0, 0);
        if (r < nvalid)
            v = *(const uint4*)(g_ah + (size_t)(rb + r) * D + c8);
        *(uint4*)(As + r * PADH + c8) = v;
    }
    // stage W1^T
#pragma unroll
    for (int it = 0; it < 4; it++) {
        int idx = tid + it * 512;
        int r = idx >> 4, c8 = (idx & 15) * 8;
        *(uint4*)(Bs + r * PADH + c8) = *(const uint4*)(g_wTh[layer] + r * D + c8);
    }
    if (tid < 128) b1s[tid] = bias1[tid];
    else if (tid < 256) b2s[tid - 128] = bias2[tid - 128];
    else if (tid < 384) {
        int r = tid - 256;
        gids[r] = (r < nvalid) ? b_at(batch, rb + r) : 0;
    }
    __syncthreads();

    float c[2][4][4];

    // ---------------- GEMM1: H1 = relu(A @ W1 + b1) ----------------
#pragma unroll
    for (int i = 0; i < 2; i++)
#pragma unroll
        for (int j = 0; j < 4; j++)
#pragma unroll
            for (int q = 0; q < 4; q++) c[i][j][q] = 0.f;

#pragma unroll
    for (int kk = 0; kk < 8; kk++) {
        int kw = kk * 8 + tig;
        uint32_t a[2][4];
#pragma unroll
        for (int i = 0; i < 2; i++) {
            int r0 = (warp_m * 32 + i * 16 + gID) * 68;
            a[i][0] = As32[r0 + kw];
            a[i][1] = As32[r0 + 8 * 68 + kw];
            a[i][2] = As32[r0 + kw + 4];
            a[i][3] = As32[r0 + 8 * 68 + kw + 4];
        }
#pragma unroll
        for (int j = 0; j < 4; j++) {
            int n = warp_n * 32 + j * 8 + gID;
            uint32_t b0 = Bs32[n * 68 + kw];
            uint32_t b1 = Bs32[n * 68 + kw + 4];
            mma_f16(c[0][j], a[0][0], a[0][1], a[0][2], a[0][3], b0, b1);
            mma_f16(c[1][j], a[1][0], a[1][1], a[1][2], a[1][3], b0, b1);
        }
    }
    __syncthreads();

    // H1 (fp16) -> As, stage W2^T -> Bs
#pragma unroll
    for (int i = 0; i < 2; i++) {
        int r0 = warp_m * 32 + i * 16 + gID;
#pragma unroll
        for (int j = 0; j < 4; j++) {
            int cb = warp_n * 32 + j * 8 + 2 * tig;
            int w = warp_n * 16 + j * 4 + tig;
            As32[r0 * 68 + w] =
                pack_h2(fmaxf(c[i][j][0] + b1s[cb], 0.f),
                        fmaxf(c[i][j][1] + b1s[cb + 1], 0.f));
            As32[(r0 + 8) * 68 + w] =
                pack_h2(fmaxf(c[i][j][2] + b1s[cb], 0.f),
                        fmaxf(c[i][j][3] + b1s[cb + 1], 0.f));
        }
    }
#pragma unroll
    for (int it = 0; it < 4; it++) {
        int idx = tid + it * 512;
        int r = idx >> 4, c8 = (idx & 15) * 8;
        *(uint4*)(Bs + r * PADH + c8) = *(const uint4*)(g_wTh[4 + layer] + r * D + c8);
    }
    __syncthreads();

    // ---------------- GEMM2: H = relu(H1 @ W2 + b2) ----------------
#pragma unroll
    for (int i = 0; i < 2; i++)
#pragma unroll
        for (int j = 0; j < 4; j++)
#pragma unroll
            for (int q = 0; q < 4; q++) c[i][j][q] = 0.f;

#pragma unroll
    for (int kk = 0; kk < 8; kk++) {
        int kw = kk * 8 + tig;
        uint32_t a[2][4];
#pragma unroll
        for (int i = 0; i < 2; i++) {
            int r0 = (warp_m * 32 + i * 16 + gID) * 68;
            a[i][0] = As32[r0 + kw];
            a[i][1] = As32[r0 + 8 * 68 + kw];
            a[i][2] = As32[r0 + kw + 4];
            a[i][3] = As32[r0 + 8 * 68 + kw + 4];
        }
#pragma unroll
        for (int j = 0; j < 4; j++) {
            int n = warp_n * 32 + j * 8 + gID;
            uint32_t b0 = Bs32[n * 68 + kw];
            uint32_t b1 = Bs32[n * 68 + kw + 4];
            mma_f16(c[0][j], a[0][0], a[0][1], a[0][2], a[0][3], b0, b1);
            mma_f16(c[1][j], a[1][0], a[1][1], a[1][2], a[1][3], b0, b1);
        }
    }
    __syncthreads();   // smem reads done; reuse ALL smem as float staging

    // epilogue: H -> global (fp16) + smem staging for stats (fp32)
    float* Hs = (float*)smh;             // [128][PAD] floats = 67.6KB
#pragma unroll
    for (int i = 0; i < 2; i++) {
        int lr0 = warp_m * 32 + i * 16 + gID;
        int lr1 = lr0 + 8;
#pragma unroll
        for (int j = 0; j < 4; j++) {
            int cb = warp_n * 32 + j * 8 + 2 * tig;
            float o00 = fmaxf(c[i][j][0] + b2s[cb], 0.f);
            float o01 = fmaxf(c[i][j][1] + b2s[cb + 1], 0.f);
            float o10 = fmaxf(c[i][j][2] + b2s[cb], 0.f);
            float o11 = fmaxf(c[i][j][3] + b2s[cb + 1], 0.f);
            Hs[lr0 * PAD + cb] = o00;  Hs[lr0 * PAD + cb + 1] = o01;
            Hs[lr1 * PAD + cb] = o10;  Hs[lr1 * PAD + cb + 1] = o11;
            if (lr0 < nvalid)
                *(uint32_t*)(g_h16 + (size_t)(rb + lr0) * D + cb) = pack_h2(o00, o01);
            if (lr1 < nvalid)
                *(uint32_t*)(g_h16 + (size_t)(rb + lr1) * D + cb) = pack_h2(o10, o11);
        }
    }
    __syncthreads();

    // per-graph stats (sum, sumsq): 4 strips of 32 rows @512thr
    {
        int d = tid & 127, strip = tid >> 7;      // 0..3
        int r0 = strip * 32, r1 = min(r0 + 32, nvalid);
        if (r0 < nvalid) {
            int curg = gids[r0];
            float s = 0.f, q = 0.f;
            for (int r = r0; r < r1; r++) {
                int g = gids[r];
                if (g != curg) {
                    atomicAdd(&g_stat[layer][curg][0][d], s);
                    atomicAdd(&g_stat[layer][curg][1][d], q);
                    s = 0.f; q = 0.f; curg = g;
                }
                float v = Hs[r * PAD + d];
                s += v; q += v * v;
            }
            atomicAdd(&g_stat[layer][curg][0][d], s);
            atomicAdd(&g_stat[layer][curg][1][d], q);
        }
    }
}

// ------------------------- GraphNorm apply + relu --------------------------
__global__ void __launch_bounds__(256) k_gnapply(const void* __restrict__ batch,
                                                 const float* __restrict__ w,
                                                 const float* __restrict__ b,
                                                 const float* __restrict__ ms,
                                                 int layer, int last) {
    int warp = (blockIdx.x * blockDim.x + threadIdx.x) >> 5;
    int lane = threadIdx.x & 31;
    if (warp >= N_NODES) return;
    int g = b_at(batch, warp);
    float c = g_gcnt[g];
    int d0 = lane * 4;
    uint2 hr = ((const uint2*)(g_h16 + (size_t)warp * D))[lane];
    float2 hf0 = __half22float2(*reinterpret_cast<__half2*>(&hr.x));
    float2 hf1 = __half22float2(*reinterpret_cast<__half2*>(&hr.y));
    float4 h = make_float4(hf0.x, hf0.y, hf1.x, hf1.y);
    float4 s4 = *(const float4*)&g_stat[layer][g][0][d0];
    float4 q4 = *(const float4*)&g_stat[layer][g][1][d0];
    float4 ms4 = *(const float4*)(ms + layer * D + d0);
    float4 w4  = *(const float4*)(w  + layer * D + d0);
    float4 b4  = *(const float4*)(b  + layer * D + d0);
    float4 o;
#define GN1(X) {                                                   \
    float mean = s4.X / c;                                         \
    float aa = mean * ms4.X;                                       \
    float var = q4.X / c - 2.f * aa * mean + aa * aa;              \
    float rstd = rsqrtf(var + GN_EPS);                             \
    o.X = fmaxf(w4.X * (h.X - aa) * rstd + b4.X, 0.f); }
    GN1(x) GN1(y) GN1(z) GN1(w)
#undef GN1
    if (last) {
        atomicAdd(&g_pool[g * D + d0 + 0], o.x);
        atomicAdd(&g_pool[g * D + d0 + 1], o.y);
        atomicAdd(&g_pool[g * D + d0 + 2], o.z);
        atomicAdd(&g_pool[g * D + d0 + 3], o.w);
    } else {
        uint2 pk;
        pk.x = pack_h2(o.x, o.y);
        pk.y = pack_h2(o.z, o.w);
        ((uint2*)(g_hh + (size_t)warp * D))[lane] = pk;
    }
}

// ------------------------- final MLP + log_softmax -------------------------
__global__ void __launch_bounds__(128) k_mlp(const float* __restrict__ fw1,
                                             const float* __restrict__ fb1,
                                             const float* __restrict__ fw2,
                                             const float* __restrict__ fb2,
                                             const float* __restrict__ fw3,
                                             const float* __restrict__ fb3,
                                             float* __restrict__ out) {
    int g = blockIdx.x, t = threadIdx.x;
    __shared__ float v[D], v2[D], o[C], red[2];
    v[t] = g_pool[g * D + t];
    __syncthreads();
    float acc = fb1[t];
    for (int k = 0; k < D; k++) acc += v[k] * fw1[k * D + t];
    v2[t] = fmaxf(acc, 0.f);
    __syncthreads();
    acc = fb2[t];
    for (int k = 0; k < D; k++) acc += v2[k] * fw2[k * D + t];
    __syncthreads();
    v[t] = fmaxf(acc, 0.f);
    __syncthreads();
    if (t < C) {
        float a = fb3[t];
        for (int k = 0; k < D; k++) a += v[k] * fw3[k * C + t];
        o[t] = a;
    }
    __syncthreads();
    if (t == 0) {
        float m = -1e30f;
        for (int cc = 0; cc < C; cc++) m = fmaxf(m, o[cc]);
        float se = 0.f;
        for (int cc = 0; cc < C; cc++) se += expf(o[cc] - m);
        red[0] = m; red[1] = logf(se);
    }
    __syncthreads();
    if (t < C) out[g * C + t] = o[t] - red[0] - red[1];
}

// ------------------------- launcher ----------------------------------------
extern "C" void kernel_launch(void* const* d_in, const int* in_sizes, int n_in,
                              void* d_out, int out_size) {
    const float* x    = (const float*)d_in[0];
    const float* w1   = (const float*)d_in[1];
    const float* b1   = (const float*)d_in[2];
    const float* w2   = (const float*)d_in[3];
    const float* b2   = (const float*)d_in[4];
    const float* gnw  = (const float*)d_in[5];
    const float* gnb  = (const float*)d_in[6];
    const float* gns  = (const float*)d_in[7];
    const float* fw1  = (const float*)d_in[8];
    const float* fb1  = (const float*)d_in[9];
    const float* fw2  = (const float*)d_in[10];
    const float* fb2  = (const float*)d_in[11];
    const float* fw3  = (const float*)d_in[12];
    const float* fb3  = (const float*)d_in[13];
    const void*  edge  = d_in[14];
    const void*  batch = d_in[15];
    float* out = (float*)d_out;

    cudaFuncSetAttribute(k_gin, cudaFuncAttributeMaxDynamicSharedMemorySize,
                         SMEM_GIN);

    // prologue: fused prep, then 3-kernel CSR build
    k_prep<<<1024, 256>>>((const int*)edge, (const int*)batch, w1, w2, x);
    k_hist<<<(N_EDGES + 255) / 256, 256>>>(edge);
    k_scan<<<NB_SCAN, 256>>>();
    k_fill<<<(N_EDGES + 255) / 256, 256>>>(edge);

    const int ginGrid = (N_NODES + 127) / 128;        // 391
    const int aggGrid = (N_NODES * 32 + 255) / 256;   // 6250

    for (int l = 0; l < L; l++) {
        k_agg<<<aggGrid, 256>>>();                        // read hh, write ah
        k_gin<<<ginGrid, 512, SMEM_GIN>>>(l,              // read ah, write h16
                                          b1 + (size_t)l * D, b2 + (size_t)l * D,
                                          batch);
        k_gnapply<<<aggGrid, 256>>>(batch, gnw, gnb, gns, l, l == L - 1);
    }
    k_mlp<<<N_GRAPHS, 128>>>(fw1, fb1, fw2, fb2, fw3, fb3, out);
}

// round 13
// speedup vs baseline: 1.8125x; 1.0647x over previous
#include <cuda_runtime.h>
#include <cuda_fp16.h>
#include <cstdint>

#define N_NODES 50000
#define N_EDGES 800000
#define N_GRAPHS 128
#define D 128
#define L 4
#define C 10
#define GN_EPS 1e-5f
#define NB_SCAN 196
#define PAD 132          // float padding (stats staging)
#define PADH 136         // half padding (GEMM tiles), 68 words/row
#define ZERO_ELEMS (L * N_GRAPHS * 2 * D)
#define GIN_TILES 391    // ceil(N_NODES/128)
#define GIN_GRID 296     // 148 SMs x 2 guaranteed-resident CTAs

// ------------------------- device scratch (static, no allocs) -------------
__device__ __half g_h16[(size_t)N_NODES * D]; // un-normalized H (fp16)
__device__ __half g_ah[(size_t)N_NODES * D];  // agg output (fp16, gin input)
__device__ __half g_hh[(size_t)N_NODES * D];  // fp16 normalized state
__device__ int    g_rowptr[N_NODES + 1];
__device__ int    g_cursor[N_NODES];
__device__ int    g_cnt[N_NODES];
__device__ int    g_col[N_EDGES];
__device__ int    g_gptr[N_GRAPHS + 1];
__device__ float  g_gcnt[N_GRAPHS];
__device__ float  g_pool[N_GRAPHS * D];
__device__ float  g_stat[L][N_GRAPHS][2][D];
__device__ __half g_wTh[8][16384];            // W^T fp16, B[n][k]
__device__ int    g_bar[L];                   // grid barrier counters
__device__ int    g_is64e;
__device__ int    g_is64b;

// ------------------------- helpers ----------------------------------------
__device__ __forceinline__ int e_at(const void* p, long long i) {
    if (g_is64e) return (int)((const long long*)p)[i];
    return ((const int*)p)[i];
}
__device__ __forceinline__ int b_at(const void* p, long long i) {
    if (g_is64b) return (int)((const long long*)p)[i];
    return ((const int*)p)[i];
}

// mma.sync m16n8k16 fp16 (fp32 accum): C += A*B
__device__ __forceinline__ void mma_f16(float c[4], uint32_t a0, uint32_t a1,
                                        uint32_t a2, uint32_t a3,
                                        uint32_t b0, uint32_t b1) {
    asm volatile(
        "mma.sync.aligned.m16n8k16.row.col.f32.f16.f16.f32 "
        "{%0,%1,%2,%3}, {%4,%5,%6,%7}, {%8,%9}, {%0,%1,%2,%3};"
        : "+f"(c[0]), "+f"(c[1]), "+f"(c[2]), "+f"(c[3])
        : "r"(a0), "r"(a1), "r"(a2), "r"(a3), "r"(b0), "r"(b1));
}

__device__ __forceinline__ void acc_h4(float4& acc, uint2 r) {
    float2 f0 = __half22float2(*reinterpret_cast<__half2*>(&r.x));
    float2 f1 = __half22float2(*reinterpret_cast<__half2*>(&r.y));
    acc.x += f0.x; acc.y += f0.y; acc.z += f1.x; acc.w += f1.y;
}
__device__ __forceinline__ uint32_t pack_h2(float x, float y) {
    __half2 h = __floats2half2_rn(x, y);
    return *reinterpret_cast<uint32_t*>(&h);
}

// --------- fused prologue: zero + detect + graphs + wT + x mirror ----------
__global__ void k_prep(const int* __restrict__ ew, const int* __restrict__ bw,
                       const float* __restrict__ w1, const float* __restrict__ w2,
                       const float* __restrict__ x) {
    int gsz = gridDim.x * blockDim.x;
    int gid0 = blockIdx.x * blockDim.x + threadIdx.x;

    if (blockIdx.x == 0) {
        __shared__ int s_ez, s_bg;
        if (threadIdx.x == 0) { s_ez = 1; s_bg = 0; }
        __syncthreads();
        for (int j = threadIdx.x; j < 128; j += blockDim.x)
            if (ew[2 * j + 1] != 0) atomicAnd(&s_ez, 0);
        for (int j = threadIdx.x; j < 24999; j += blockDim.x)
            if (bw[2 * j] > bw[2 * j + 1]) atomicOr(&s_bg, 1);
        __syncthreads();
        if (threadIdx.x == 0) {
            g_is64e = s_ez; g_is64b = s_bg;
            for (int l = 0; l < L; l++) g_bar[l] = 0;
        }
        if (threadIdx.x < N_GRAPHS) {
            int g = threadIdx.x;
            int lo = 0, hi = N_NODES;
            while (lo < hi) {
                int mid = (lo + hi) >> 1;
                int v = s_bg ? (int)((const long long*)bw)[mid] : bw[mid];
                if (v < g) lo = mid + 1; else hi = mid;
            }
            g_gptr[g] = lo;
            if (g == 0) g_gptr[N_GRAPHS] = N_NODES;
        }
        __syncthreads();
        if (threadIdx.x < N_GRAPHS) {
            int g = threadIdx.x;
            int nxt = (g < N_GRAPHS - 1) ? g_gptr[g + 1] : N_NODES;
            g_gcnt[g] = fmaxf((float)(nxt - g_gptr[g]), 1.0f);
        }
    }

    for (int i = gid0; i < ZERO_ELEMS; i += gsz) {
        if (i < N_NODES) g_cnt[i] = 0;
        (&g_stat[0][0][0][0])[i] = 0.f;
        if (i < N_GRAPHS * D) g_pool[i] = 0.f;
    }
    for (int i = gid0; i < 8 * 16384; i += gsz) {
        int m = i >> 14, idx = i & 16383;
        int k = idx >> 7, n = idx & 127;
        const float* W = (m < 4) ? (w1 + (size_t)m * D * D)
                                 : (w2 + (size_t)(m - 4) * D * D);
        g_wTh[m][n * D + k] = __float2half(W[idx]);
    }
    for (int i = gid0; i < N_NODES * D / 4; i += gsz) {
        float4 v = *(const float4*)(x + (size_t)i * 4);
        uint2 pk;
        pk.x = pack_h2(v.x, v.y);
        pk.y = pack_h2(v.z, v.w);
        ((uint2*)g_hh)[i] = pk;
    }
}

// ------------------------- CSR build ---------------------------------------
__global__ void k_hist(const void* __restrict__ e) {
    int i = blockIdx.x * blockDim.x + threadIdx.x;
    if (i < N_EDGES) atomicAdd(&g_cnt[e_at(e, (long long)N_EDGES + i)], 1);
}

__global__ void k_scan() {
    __shared__ int red[256];
    int t = threadIdx.x, b = blockIdx.x;
    int idx = b * 256 + t;

    int base = 0;
    for (int i = t; i < b * 256; i += 256) base += g_cnt[i];
    red[t] = base;
    __syncthreads();
    for (int off = 128; off > 0; off >>= 1) {
        if (t < off) red[t] += red[t + off];
        __syncthreads();
    }
    int blockBase = red[0];
    __syncthreads();

    int v = (idx < N_NODES) ? g_cnt[idx] : 0;
    red[t] = v;
    __syncthreads();
    for (int off = 1; off < 256; off <<= 1) {
        int u = (t >= off) ? red[t - off] : 0;
        __syncthreads(); red[t] += u; __syncthreads();
    }
    if (idx < N_NODES) {
        int rp = blockBase + red[t] - v;
        g_rowptr[idx] = rp; g_cursor[idx] = rp;
    }
    if (b == NB_SCAN - 1 && t == 255) g_rowptr[N_NODES] = blockBase + red[255];
}

__global__ void k_fill(const void* __restrict__ e) {
    int i = blockIdx.x * blockDim.x + threadIdx.x;
    if (i < N_EDGES) {
        int s = e_at(e, i);
        int d = e_at(e, (long long)N_EDGES + i);
        g_col[atomicAdd(&g_cursor[d], 1)] = s;
    }
}

// ------------------------- aggregation (fp16 in, fp16 out) -----------------
__global__ void __launch_bounds__(256) k_agg() {
    int warp = (blockIdx.x * blockDim.x + threadIdx.x) >> 5;
    int lane = threadIdx.x & 31;
    if (warp >= N_NODES) return;
    int s = g_rowptr[warp], e = g_rowptr[warp + 1];
    float4 acc = make_float4(0.f, 0.f, 0.f, 0.f);
    acc_h4(acc, __ldg(((const uint2*)(g_hh + (size_t)warp * D)) + lane));
    int i = s;
    for (; i + 4 <= e; i += 4) {
        int s0 = g_col[i], s1 = g_col[i + 1], s2 = g_col[i + 2], s3 = g_col[i + 3];
        uint2 r0 = __ldg(((const uint2*)(g_hh + (size_t)s0 * D)) + lane);
        uint2 r1 = __ldg(((const uint2*)(g_hh + (size_t)s1 * D)) + lane);
        uint2 r2 = __ldg(((const uint2*)(g_hh + (size_t)s2 * D)) + lane);
        uint2 r3 = __ldg(((const uint2*)(g_hh + (size_t)s3 * D)) + lane);
        acc_h4(acc, r0); acc_h4(acc, r1); acc_h4(acc, r2); acc_h4(acc, r3);
    }
    for (; i < e; i++)
        acc_h4(acc, __ldg(((const uint2*)(g_hh + (size_t)g_col[i] * D)) + lane));
    uint2 pk;
    pk.x = pack_h2(acc.x, acc.y);
    pk.y = pack_h2(acc.z, acc.w);
    ((uint2*)(g_ah + (size_t)warp * D))[lane] = pk;
}

// ---- persistent fused GIN layer + GraphNorm apply -------------------------
// 296 CTAs, __launch_bounds__(512,2) => provably all resident (smem 69.6KB
// fits 2/SM, regs capped) => software grid barrier is deadlock-free.
#define SMEM_GIN ((128 * PADH + 128 * PADH) * 2)

__global__ void __launch_bounds__(512, 2) k_gin(int layer,
                                                const float* __restrict__ bias1,
                                                const float* __restrict__ bias2,
                                                const void* __restrict__ batch,
                                                const float* __restrict__ gnw,
                                                const float* __restrict__ gnb,
                                                const float* __restrict__ gns,
                                                int last) {
    extern __shared__ __half smh[];
    __half* As = smh;                    // [128][PADH]
    __half* Bs = smh + 128 * PADH;       // [128][PADH]
    uint32_t* As32 = (uint32_t*)As;
    uint32_t* Bs32 = (uint32_t*)Bs;
    __shared__ float b1s[128], b2s[128];
    __shared__ int gids[128];

    int tid = threadIdx.x, lane = tid & 31, wid = tid >> 5;
    int warp_m = wid & 3, warp_n = wid >> 2;     // 4 x 4 warp grid, 32x32 tiles
    int gID = lane >> 2, tig = lane & 3;

    // ---------------- phase 1: GEMM tiles + stats ----------------
    for (int t = blockIdx.x; t < GIN_TILES; t += GIN_GRID) {
        int rb = t * 128;
        int nvalid = min(128, N_NODES - rb);

#pragma unroll
        for (int it = 0; it < 4; it++) {          // stage A
            int idx = tid + it * 512;
            int r = idx >> 4, c8 = (idx & 15) * 8;
            uint4 v = make_uint4(0, 0, 0, 0);
            if (r < nvalid)
                v = *(const uint4*)(g_ah + (size_t)(rb + r) * D + c8);
            *(uint4*)(As + r * PADH + c8) = v;
        }
#pragma unroll
        for (int it = 0; it < 4; it++) {          // stage W1^T
            int idx = tid + it * 512;
            int r = idx >> 4, c8 = (idx & 15) * 8;
            *(uint4*)(Bs + r * PADH + c8) = *(const uint4*)(g_wTh[layer] + r * D + c8);
        }
        if (tid < 128) b1s[tid] = bias1[tid];
        else if (tid < 256) b2s[tid - 128] = bias2[tid - 128];
        else if (tid < 384) {
            int r = tid - 256;
            gids[r] = (r < nvalid) ? b_at(batch, rb + r) : 0;
        }
        __syncthreads();

        float c[2][4][4];
#pragma unroll
        for (int i = 0; i < 2; i++)
#pragma unroll
            for (int j = 0; j < 4; j++)
#pragma unroll
                for (int q = 0; q < 4; q++) c[i][j][q] = 0.f;

        // GEMM1
#pragma unroll
        for (int kk = 0; kk < 8; kk++) {
            int kw = kk * 8 + tig;
            uint32_t a[2][4];
#pragma unroll
            for (int i = 0; i < 2; i++) {
                int r0 = (warp_m * 32 + i * 16 + gID) * 68;
                a[i][0] = As32[r0 + kw];
                a[i][1] = As32[r0 + 8 * 68 + kw];
                a[i][2] = As32[r0 + kw + 4];
                a[i][3] = As32[r0 + 8 * 68 + kw + 4];
            }
#pragma unroll
            for (int j = 0; j < 4; j++) {
                int n = warp_n * 32 + j * 8 + gID;
                uint32_t b0 = Bs32[n * 68 + kw];
                uint32_t b1 = Bs32[n * 68 + kw + 4];
                mma_f16(c[0][j], a[0][0], a[0][1], a[0][2], a[0][3], b0, b1);
                mma_f16(c[1][j], a[1][0], a[1][1], a[1][2], a[1][3], b0, b1);
            }
        }
        __syncthreads();

        // H1 -> As, stage W2^T -> Bs
#pragma unroll
        for (int i = 0; i < 2; i++) {
            int r0 = warp_m * 32 + i * 16 + gID;
#pragma unroll
            for (int j = 0; j < 4; j++) {
                int cb = warp_n * 32 + j * 8 + 2 * tig;
                int w = warp_n * 16 + j * 4 + tig;
                As32[r0 * 68 + w] =
                    pack_h2(fmaxf(c[i][j][0] + b1s[cb], 0.f),
                            fmaxf(c[i][j][1] + b1s[cb + 1], 0.f));
                As32[(r0 + 8) * 68 + w] =
                    pack_h2(fmaxf(c[i][j][2] + b1s[cb], 0.f),
                            fmaxf(c[i][j][3] + b1s[cb + 1], 0.f));
            }
        }
#pragma unroll
        for (int it = 0; it < 4; it++) {
            int idx = tid + it * 512;
            int r = idx >> 4, c8 = (idx & 15) * 8;
            *(uint4*)(Bs + r * PADH + c8) = *(const uint4*)(g_wTh[4 + layer] + r * D + c8);
        }
        __syncthreads();

        // GEMM2
#pragma unroll
        for (int i = 0; i < 2; i++)
#pragma unroll
            for (int j = 0; j < 4; j++)
#pragma unroll
                for (int q = 0; q < 4; q++) c[i][j][q] = 0.f;

#pragma unroll
        for (int kk = 0; kk < 8; kk++) {
            int kw = kk * 8 + tig;
            uint32_t a[2][4];
#pragma unroll
            for (int i = 0; i < 2; i++) {
                int r0 = (warp_m * 32 + i * 16 + gID) * 68;
                a[i][0] = As32[r0 + kw];
                a[i][1] = As32[r0 + 8 * 68 + kw];
                a[i][2] = As32[r0 + kw + 4];
                a[i][3] = As32[r0 + 8 * 68 + kw + 4];
            }
#pragma unroll
            for (int j = 0; j < 4; j++) {
                int n = warp_n * 32 + j * 8 + gID;
                uint32_t b0 = Bs32[n * 68 + kw];
                uint32_t b1 = Bs32[n * 68 + kw + 4];
                mma_f16(c[0][j], a[0][0], a[0][1], a[0][2], a[0][3], b0, b1);
                mma_f16(c[1][j], a[1][0], a[1][1], a[1][2], a[1][3], b0, b1);
            }
        }
        __syncthreads();

        // epilogue: H -> g_h16 + smem float staging for stats
        float* Hs = (float*)smh;
#pragma unroll
        for (int i = 0; i < 2; i++) {
            int lr0 = warp_m * 32 + i * 16 + gID;
            int lr1 = lr0 + 8;
#pragma unroll
            for (int j = 0; j < 4; j++) {
                int cb = warp_n * 32 + j * 8 + 2 * tig;
                float o00 = fmaxf(c[i][j][0] + b2s[cb], 0.f);
                float o01 = fmaxf(c[i][j][1] + b2s[cb + 1], 0.f);
                float o10 = fmaxf(c[i][j][2] + b2s[cb], 0.f);
                float o11 = fmaxf(c[i][j][3] + b2s[cb + 1], 0.f);
                Hs[lr0 * PAD + cb] = o00;  Hs[lr0 * PAD + cb + 1] = o01;
                Hs[lr1 * PAD + cb] = o10;  Hs[lr1 * PAD + cb + 1] = o11;
                if (lr0 < nvalid)
                    *(uint32_t*)(g_h16 + (size_t)(rb + lr0) * D + cb) = pack_h2(o00, o01);
                if (lr1 < nvalid)
                    *(uint32_t*)(g_h16 + (size_t)(rb + lr1) * D + cb) = pack_h2(o10, o11);
            }
        }
        __syncthreads();

        // per-graph stats
        {
            int d = tid & 127, strip = tid >> 7;
            int r0 = strip * 32, r1 = min(r0 + 32, nvalid);
            if (r0 < nvalid) {
                int curg = gids[r0];
                float s = 0.f, q = 0.f;
                for (int r = r0; r < r1; r++) {
                    int g = gids[r];
                    if (g != curg) {
                        atomicAdd(&g_stat[layer][curg][0][d], s);
                        atomicAdd(&g_stat[layer][curg][1][d], q);
                        s = 0.f; q = 0.f; curg = g;
                    }
                    float v = Hs[r * PAD + d];
                    s += v; q += v * v;
                }
                atomicAdd(&g_stat[layer][curg][0][d], s);
                atomicAdd(&g_stat[layer][curg][1][d], q);
            }
        }
        __syncthreads();   // before next tile overwrites smem
    }

    // ---------------- grid barrier (deadlock-free: all CTAs resident) ------
    __threadfence();
    __syncthreads();
    if (tid == 0) {
        atomicAdd(&g_bar[layer], 1);
        while (atomicAdd(&g_bar[layer], 0) < GIN_GRID)
            __nanosleep(64);
    }
    __syncthreads();
    __threadfence();

    // ---------------- phase 2: GraphNorm apply on own tiles ----------------
    for (int t = blockIdx.x; t < GIN_TILES; t += GIN_GRID) {
        int rb = t * 128;
        int nvalid = min(128, N_NODES - rb);
        for (int rr = wid; rr < nvalid; rr += 16) {
            int r = rb + rr;
            int g = b_at(batch, r);
            float cgc = g_gcnt[g];
            int d0 = lane * 4;
            uint2 hr = ((const uint2*)(g_h16 + (size_t)r * D))[lane];
            float2 hf0 = __half22float2(*reinterpret_cast<__half2*>(&hr.x));
            float2 hf1 = __half22float2(*reinterpret_cast<__half2*>(&hr.y));
            float4 h = make_float4(hf0.x, hf0.y, hf1.x, hf1.y);
            float4 s4 = *(const float4*)&g_stat[layer][g][0][d0];
            float4 q4 = *(const float4*)&g_stat[layer][g][1][d0];
            float4 ms4 = *(const float4*)(gns + layer * D + d0);
            float4 w4  = *(const float4*)(gnw + layer * D + d0);
            float4 b4  = *(const float4*)(gnb + layer * D + d0);
            float4 o;
#define GN1(X) {                                                   \
    float mean = s4.X / cgc;                                       \
    float aa = mean * ms4.X;                                       \
    float var = q4.X / cgc - 2.f * aa * mean + aa * aa;            \
    float rstd = rsqrtf(var + GN_EPS);                             \
    o.X = fmaxf(w4.X * (h.X - aa) * rstd + b4.X, 0.f); }
            GN1(x) GN1(y) GN1(z) GN1(w)
#undef GN1
            if (last) {
                atomicAdd(&g_pool[g * D + d0 + 0], o.x);
                atomicAdd(&g_pool[g * D + d0 + 1], o.y);
                atomicAdd(&g_pool[g * D + d0 + 2], o.z);
                atomicAdd(&g_pool[g * D + d0 + 3], o.w);
            } else {
                uint2 pk;
                pk.x = pack_h2(o.x, o.y);
                pk.y = pack_h2(o.z, o.w);
                ((uint2*)(g_hh + (size_t)r * D))[lane] = pk;
            }
        }
    }
}

// ------------------------- final MLP + log_softmax -------------------------
__global__ void __launch_bounds__(128) k_mlp(const float* __restrict__ fw1,
                                             const float* __restrict__ fb1,
                                             const float* __restrict__ fw2,
                                             const float* __restrict__ fb2,
                                             const float* __restrict__ fw3,
                                             const float* __restrict__ fb3,
                                             float* __restrict__ out) {
    int g = blockIdx.x, t = threadIdx.x;
    __shared__ float v[D], v2[D], o[C], red[2];
    v[t] = g_pool[g * D + t];
    __syncthreads();
    float acc = fb1[t];
    for (int k = 0; k < D; k++) acc += v[k] * fw1[k * D + t];
    v2[t] = fmaxf(acc, 0.f);
    __syncthreads();
    acc = fb2[t];
    for (int k = 0; k < D; k++) acc += v2[k] * fw2[k * D + t];
    __syncthreads();
    v[t] = fmaxf(acc, 0.f);
    __syncthreads();
    if (t < C) {
        float a = fb3[t];
        for (int k = 0; k < D; k++) a += v[k] * fw3[k * C + t];
        o[t] = a;
    }
    __syncthreads();
    if (t == 0) {
        float m = -1e30f;
        for (int cc = 0; cc < C; cc++) m = fmaxf(m, o[cc]);
        float se = 0.f;
        for (int cc = 0; cc < C; cc++) se += expf(o[cc] - m);
        red[0] = m; red[1] = logf(se);
    }
    __syncthreads();
    if (t < C) out[g * C + t] = o[t] - red[0] - red[1];
}

// ------------------------- launcher ----------------------------------------
extern "C" void kernel_launch(void* const* d_in, const int* in_sizes, int n_in,
                              void* d_out, int out_size) {
    const float* x    = (const float*)d_in[0];
    const float* w1   = (const float*)d_in[1];
    const float* b1   = (const float*)d_in[2];
    const float* w2   = (const float*)d_in[3];
    const float* b2   = (const float*)d_in[4];
    const float* gnw  = (const float*)d_in[5];
    const float* gnb  = (const float*)d_in[6];
    const float* gns  = (const float*)d_in[7];
    const float* fw1  = (const float*)d_in[8];
    const float* fb1  = (const float*)d_in[9];
    const float* fw2  = (const float*)d_in[10];
    const float* fb2  = (const float*)d_in[11];
    const float* fw3  = (const float*)d_in[12];
    const float* fb3  = (const float*)d_in[13];
    const void*  edge  = d_in[14];
    const void*  batch = d_in[15];
    float* out = (float*)d_out;

    cudaFuncSetAttribute(k_gin, cudaFuncAttributeMaxDynamicSharedMemorySize,
                         SMEM_GIN);

    // prologue: fused prep, then CSR build
    k_prep<<<1024, 256>>>((const int*)edge, (const int*)batch, w1, w2, x);
    k_hist<<<(N_EDGES + 255) / 256, 256>>>(edge);
    k_scan<<<NB_SCAN, 256>>>();
    k_fill<<<(N_EDGES + 255) / 256, 256>>>(edge);

    const int aggGrid = (N_NODES * 32 + 255) / 256;   // 6250

    for (int l = 0; l < L; l++) {
        k_agg<<<aggGrid, 256>>>();                    // read hh, write ah
        k_gin<<<GIN_GRID, 512, SMEM_GIN>>>(l,         // read ah, write hh/pool
                                           b1 + (size_t)l * D, b2 + (size_t)l * D,
                                           batch, gnw, gnb, gns, l == L - 1);
    }
    k_mlp<<<N_GRAPHS, 128>>>(fw1, fb1, fw2, fb2, fw3, fb3, out);
}